// round 14
// baseline (speedup 1.0000x reference)
#include <cuda_runtime.h>
#include <cuda_bf16.h>
#include <cstdint>

#define NN 100000
#define NH 20000
#define NE 1600000
#define DD 128
#define HH 512

#define NB_HE 20      // ceil(NH/1024)
#define NB_NODE 98    // ceil(NN/1024)

// ---------------- scratch (device globals; no allocation allowed) ----------------
__device__ __align__(16) int g_degi_node[NN];
__device__ __align__(16) int g_degi_he[NH];
__device__ __align__(16) int g_off_node[NN];   // after k_place: off[w] = orig off[w+1]
__device__ __align__(16) int g_off_he[NH];
__device__ __align__(16) int g_bsum[NB_HE + NB_NODE];
__device__ __align__(16) int g_srt_src[NE];     // edges sorted by dst -> src ids
__device__ __align__(16) int g_srt_dst[NE];     // edges sorted by src -> dst ids
__device__ __align__(16) float g_hyper_acc[NH * DD];
__device__ __align__(16) float g_hyper_msg[NH * DD];
__device__ __align__(16) float g_node_acc[NN * DD];
// pre-transposed bf16 hi/lo weight planes: [n][k] layout
__device__ __align__(16) __nv_bfloat16 g_w1t_h[DD * DD];
__device__ __align__(16) __nv_bfloat16 g_w1t_l[DD * DD];
__device__ __align__(16) __nv_bfloat16 g_w2t_h[DD * DD];
__device__ __align__(16) __nv_bfloat16 g_w2t_l[DD * DD];
__device__ __align__(16) __nv_bfloat16 g_w3t_h[HH * DD];   // [n=0..511][k=0..127]
__device__ __align__(16) __nv_bfloat16 g_w3t_l[HH * DD];
__device__ __align__(16) __nv_bfloat16 g_w4t_h[DD * HH];   // [n=0..127][kk=0..511]
__device__ __align__(16) __nv_bfloat16 g_w4t_l[DD * HH];

// =================== preprocessing kernels ===================
// blocks [0,160): tiled weight transpose+hi/lo; blocks [160,288): zero degree counters
__global__ void k_init(const float* __restrict__ W1, const float* __restrict__ W2,
                       const float* __restrict__ W3, const float* __restrict__ W4) {
    int b = blockIdx.x;
    if (b >= 160) {
        int idx = (b - 160) * 256 + threadIdx.x;
        int nthr = 128 * 256;
        for (int i = idx; i < NN; i += nthr) g_degi_node[i] = 0;
        for (int i = idx; i < NH; i += nthr) g_degi_he[i] = 0;
        return;
    }
    __shared__ float tile[32][33];
    const float* srcm;
    __nv_bfloat16 *dH, *dL;
    int kdim, ndim, local;
    if (b < 16)       { srcm = W1; dH = g_w1t_h; dL = g_w1t_l; kdim = 128; ndim = 128; local = b; }
    else if (b < 32)  { srcm = W2; dH = g_w2t_h; dL = g_w2t_l; kdim = 128; ndim = 128; local = b - 16; }
    else if (b < 96)  { srcm = W3; dH = g_w3t_h; dL = g_w3t_l; kdim = 128; ndim = 512; local = b - 32; }
    else              { srcm = W4; dH = g_w4t_h; dL = g_w4t_l; kdim = 512; ndim = 128; local = b - 96; }
    int ktiles = kdim >> 5;
    int kt = local % ktiles, nt = local / ktiles;
    int tx = threadIdx.x & 31, ty = threadIdx.x >> 5;
#pragma unroll
    for (int p = 0; p < 4; p++) {
        int r = p * 8 + ty;
        tile[r][tx] = srcm[(kt * 32 + r) * ndim + nt * 32 + tx];
    }
    __syncthreads();
#pragma unroll
    for (int p = 0; p < 4; p++) {
        int rr = p * 8 + ty;             // n-direction
        float v = tile[tx][rr];          // k = kt*32+tx
        __nv_bfloat16 hi = __float2bfloat16(v);
        int o = (nt * 32 + rr) * kdim + kt * 32 + tx;
        dH[o] = hi;
        dL[o] = __float2bfloat16(v - __bfloat162float(hi));
    }
}

// vectorized: 4 edges per thread via int4
__global__ void k_deg(const int* __restrict__ src, const int* __restrict__ dst) {
    int i = blockIdx.x * blockDim.x + threadIdx.x;
    if (i < NE / 4) {
        int4 s4 = ((const int4*)src)[i];
        int4 d4 = ((const int4*)dst)[i];
        atomicAdd(&g_degi_node[s4.x], 1);
        atomicAdd(&g_degi_node[s4.y], 1);
        atomicAdd(&g_degi_node[s4.z], 1);
        atomicAdd(&g_degi_node[s4.w], 1);
        atomicAdd(&g_degi_he[d4.x], 1);
        atomicAdd(&g_degi_he[d4.y], 1);
        atomicAdd(&g_degi_he[d4.z], 1);
        atomicAdd(&g_degi_he[d4.w], 1);
    }
}

// ---- 2-pass multi-block exclusive scan (blocks 0..NB_HE-1: he, rest: node) ----
__global__ void k_scan_p1() {
    int b = blockIdx.x;
    const int* __restrict__ cnt;
    int* __restrict__ off;
    int n, lb;
    if (b < NB_HE) { cnt = g_degi_he; off = g_off_he; n = NH; lb = b; }
    else           { cnt = g_degi_node; off = g_off_node; n = NN; lb = b - NB_HE; }
    __shared__ int sh[1024];
    int tid = threadIdx.x;
    int i = lb * 1024 + tid;
    int v = (i < n) ? cnt[i] : 0;
    sh[tid] = v;
    __syncthreads();
    for (int o = 1; o < 1024; o <<= 1) {
        int t = (tid >= o) ? sh[tid - o] : 0;
        __syncthreads();
        sh[tid] += t;
        __syncthreads();
    }
    if (i < n) off[i] = sh[tid] - v;
    if (tid == 1023) g_bsum[b] = sh[1023];
}

// each block computes its base via parallel 128-thread reduction of block totals
__global__ void k_scan_p2p3() {
    __shared__ int red[128];
    int b = blockIdx.x;
    int* __restrict__ off;
    int n, lb, lo;
    if (b < NB_HE) { off = g_off_he; n = NH; lb = b; lo = 0; }
    else           { off = g_off_node; n = NN; lb = b - NB_HE; lo = NB_HE; }
    int tid = threadIdx.x;
    if (tid < 128) {
        int i = lo + tid;
        red[tid] = (i < b) ? g_bsum[i] : 0;
    }
    __syncthreads();
    if (tid < 64) red[tid] += red[tid + 64];
    __syncthreads();
    if (tid < 32) {
        int s = red[tid] + red[tid + 32];
#pragma unroll
        for (int o = 16; o; o >>= 1) s += __shfl_xor_sync(0xffffffffu, s, o);
        if (tid == 0) red[0] = s;
    }
    __syncthreads();
    int add = red[0];
    int i = lb * 1024 + tid;
    if (i < n) off[i] += add;
}

// atomicAdd directly on off (slot = returned value); vectorized int4 edge loads
__global__ void k_place(const int* __restrict__ src, const int* __restrict__ dst) {
    int i = blockIdx.x * blockDim.x + threadIdx.x;
    if (i < NE / 4) {
        int4 s4 = ((const int4*)src)[i];
        int4 d4 = ((const int4*)dst)[i];
        g_srt_src[atomicAdd(&g_off_he[d4.x], 1)] = s4.x;
        g_srt_src[atomicAdd(&g_off_he[d4.y], 1)] = s4.y;
        g_srt_src[atomicAdd(&g_off_he[d4.z], 1)] = s4.z;
        g_srt_src[atomicAdd(&g_off_he[d4.w], 1)] = s4.w;
        g_srt_dst[atomicAdd(&g_off_node[s4.x], 1)] = d4.x;
        g_srt_dst[atomicAdd(&g_off_node[s4.y], 1)] = d4.y;
        g_srt_dst[atomicAdd(&g_off_node[s4.z], 1)] = d4.z;
        g_srt_dst[atomicAdd(&g_off_node[s4.w], 1)] = d4.w;
    }
}

// =================== segmented gathers (no atomics) — R12 best-known form ========
__global__ void k_gather1(const float* __restrict__ h) {
    int w = (blockIdx.x * blockDim.x + threadIdx.x) >> 5;
    if (w >= NH) return;
    int lane = threadIdx.x & 31;
    int beg = w ? g_off_he[w - 1] : 0, end = g_off_he[w];
    float4 acc = make_float4(0.f, 0.f, 0.f, 0.f);
    int e = beg;
    while (end - e >= 32) {
        int idx = g_srt_src[e + lane];
        float cnl = rsqrtf(fmaxf((float)g_degi_node[idx], 1.f));
#pragma unroll
        for (int j = 0; j < 32; j++) {
            int s = __shfl_sync(0xffffffffu, idx, j);
            float c = __shfl_sync(0xffffffffu, cnl, j);
            float4 v = __ldg(&((const float4*)h)[s * 32 + lane]);
            acc.x = fmaf(c, v.x, acc.x);
            acc.y = fmaf(c, v.y, acc.y);
            acc.z = fmaf(c, v.z, acc.z);
            acc.w = fmaf(c, v.w, acc.w);
        }
        e += 32;
    }
    int n = end - e;
    if (n > 0) {
        int idx = g_srt_src[e + (lane < n ? lane : 0)];
        float cnl = rsqrtf(fmaxf((float)g_degi_node[idx], 1.f));
#pragma unroll 4
        for (int j = 0; j < n; j++) {
            int s = __shfl_sync(0xffffffffu, idx, j);
            float c = __shfl_sync(0xffffffffu, cnl, j);
            float4 v = __ldg(&((const float4*)h)[s * 32 + lane]);
            acc.x = fmaf(c, v.x, acc.x);
            acc.y = fmaf(c, v.y, acc.y);
            acc.z = fmaf(c, v.z, acc.z);
            acc.w = fmaf(c, v.w, acc.w);
        }
    }
    ((float4*)g_hyper_acc)[w * 32 + lane] = acc;
}

__global__ void k_gather2() {
    int w = (blockIdx.x * blockDim.x + threadIdx.x) >> 5;
    if (w >= NN) return;
    int lane = threadIdx.x & 31;
    int beg = w ? g_off_node[w - 1] : 0, end = g_off_node[w];
    float4 acc = make_float4(0.f, 0.f, 0.f, 0.f);
    int e = beg;
    while (end - e >= 32) {
        int idx = g_srt_dst[e + lane];
#pragma unroll
        for (int j = 0; j < 32; j++) {
            int d = __shfl_sync(0xffffffffu, idx, j);
            float4 v = __ldg(&((const float4*)g_hyper_msg)[d * 32 + lane]);
            acc.x += v.x; acc.y += v.y; acc.z += v.z; acc.w += v.w;
        }
        e += 32;
    }
    int n = end - e;
    if (n > 0) {
        int idx = g_srt_dst[e + (lane < n ? lane : 0)];
#pragma unroll 4
        for (int j = 0; j < n; j++) {
            int d = __shfl_sync(0xffffffffu, idx, j);
            float4 v = __ldg(&((const float4*)g_hyper_msg)[d * 32 + lane]);
            acc.x += v.x; acc.y += v.y; acc.z += v.z; acc.w += v.w;
        }
    }
    ((float4*)g_node_acc)[w * 32 + lane] = acc;
}

// =================== HMMA machinery ===================
#define STR 272

__device__ __forceinline__ void mma_bf16(float d[4], uint32_t a0, uint32_t a1,
                                         uint32_t a2, uint32_t a3,
                                         uint32_t b0, uint32_t b1) {
    asm volatile(
        "mma.sync.aligned.m16n8k16.row.col.f32.bf16.bf16.f32 "
        "{%0,%1,%2,%3}, {%4,%5,%6,%7}, {%8,%9}, {%0,%1,%2,%3};"
        : "+f"(d[0]), "+f"(d[1]), "+f"(d[2]), "+f"(d[3])
        : "r"(a0), "r"(a1), "r"(a2), "r"(a3), "r"(b0), "r"(b1));
}

__device__ __forceinline__ void ldsm_x4(uint32_t r[4], uint32_t a) {
    asm volatile("ldmatrix.sync.aligned.m8n8.x4.shared.b16 {%0,%1,%2,%3}, [%4];"
                 : "=r"(r[0]), "=r"(r[1]), "=r"(r[2]), "=r"(r[3]) : "r"(a));
}

__device__ __forceinline__ void sts_hilo(char* pH, char* pL, float x0, float x1) {
    __nv_bfloat16 h0 = __float2bfloat16(x0), h1 = __float2bfloat16(x1);
    float r0f = x0 - __bfloat162float(h0), r1f = x1 - __bfloat162float(h1);
    *(__nv_bfloat162*)pH = __halves2bfloat162(h0, h1);
    *(__nv_bfloat162*)pL = __halves2bfloat162(__float2bfloat16(r0f), __float2bfloat16(r1f));
}

// D[32 warp-rows x 64 warp-cols] += A[32x128] @ W^T[64x128], 3-term hi/lo, ldmatrix loads.
__device__ __forceinline__ void gemm32x64(const char* smc, int aHoff, int aLoff,
                                          int wHoff, int wLoff,
                                          int R0, int C0, int lane,
                                          float d[2][8][4]) {
    uint32_t base = (uint32_t)__cvta_generic_to_shared(smc);
    uint32_t aH = base + aHoff + (R0 + (lane & 15)) * STR + ((lane >> 4) & 1) * 16;
    uint32_t aL = aH + (aLoff - aHoff);
    int brow = C0 + (lane & 7) + ((lane >> 4) & 1) * 8;
    uint32_t bH = base + wHoff + brow * STR + ((lane >> 3) & 1) * 16;
    uint32_t bL = bH + (wLoff - wHoff);
#pragma unroll 2
    for (int k = 0; k < 8; k++) {
        uint32_t ah0[4], ah1[4], al0[4], al1[4];
        ldsm_x4(ah0, aH);
        ldsm_x4(ah1, aH + 16 * STR);
        ldsm_x4(al0, aL);
        ldsm_x4(al1, aL + 16 * STR);
#pragma unroll
        for (int jp = 0; jp < 4; jp++) {
            uint32_t bh[4], bl[4];
            ldsm_x4(bh, bH + jp * 16 * STR);
            ldsm_x4(bl, bL + jp * 16 * STR);
            int j0 = 2 * jp, j1 = 2 * jp + 1;
            mma_bf16(d[0][j0], ah0[0], ah0[1], ah0[2], ah0[3], bh[0], bh[1]);
            mma_bf16(d[0][j0], al0[0], al0[1], al0[2], al0[3], bh[0], bh[1]);
            mma_bf16(d[0][j0], ah0[0], ah0[1], ah0[2], ah0[3], bl[0], bl[1]);
            mma_bf16(d[1][j0], ah1[0], ah1[1], ah1[2], ah1[3], bh[0], bh[1]);
            mma_bf16(d[1][j0], al1[0], al1[1], al1[2], al1[3], bh[0], bh[1]);
            mma_bf16(d[1][j0], ah1[0], ah1[1], ah1[2], ah1[3], bl[0], bl[1]);
            mma_bf16(d[0][j1], ah0[0], ah0[1], ah0[2], ah0[3], bh[2], bh[3]);
            mma_bf16(d[0][j1], al0[0], al0[1], al0[2], al0[3], bh[2], bh[3]);
            mma_bf16(d[0][j1], ah0[0], ah0[1], ah0[2], ah0[3], bl[2], bl[3]);
            mma_bf16(d[1][j1], ah1[0], ah1[1], ah1[2], ah1[3], bh[2], bh[3]);
            mma_bf16(d[1][j1], al1[0], al1[1], al1[2], al1[3], bh[2], bh[3]);
            mma_bf16(d[1][j1], ah1[0], ah1[1], ah1[2], ah1[3], bl[2], bl[3]);
        }
        aH += 32; aL += 32; bH += 32; bL += 32;
    }
}

// async W staging: issue LDGSTS then overlap other work; wait with W_WAIT before use
__device__ __forceinline__ void stage_w_async(char* smc, int wHoff, int wLoff,
                                              const __nv_bfloat16* srcH,
                                              const __nv_bfloat16* srcL, int srcStride) {
    int tid = threadIdx.x;
    unsigned dH = (unsigned)__cvta_generic_to_shared(smc + wHoff);
    unsigned dL = (unsigned)__cvta_generic_to_shared(smc + wLoff);
#pragma unroll
    for (int i = tid; i < 2048; i += 256) {
        int r = i >> 4, c8 = (i & 15) * 8;
        asm volatile("cp.async.cg.shared.global [%0], [%1], 16;"
                     :: "r"(dH + r * STR + c8 * 2), "l"(srcH + r * srcStride + c8) : "memory");
        asm volatile("cp.async.cg.shared.global [%0], [%1], 16;"
                     :: "r"(dL + r * STR + c8 * 2), "l"(srcL + r * srcStride + c8) : "memory");
    }
    asm volatile("cp.async.commit_group;" ::: "memory");
}
#define W_WAIT() asm volatile("cp.async.wait_group 0;" ::: "memory")

// ---- GEMM1 (hyper): g_hyper_msg = ch^2*(hyper_acc @ W1) + ch*b1 ----
#define SM1_CH 0
#define SM1_B1 512
#define SM1_AH 1024
#define SM1_AL (SM1_AH + 128 * STR)
#define SM1_WH (SM1_AL + 128 * STR)
#define SM1_WL (SM1_WH + 128 * STR)
#define SM1_TOTAL (SM1_WL + 128 * STR)

__global__ __launch_bounds__(256, 1) void k_gemm1_mma(const float* __restrict__ b1f) {
    extern __shared__ char smc[];
    const int tid = threadIdx.x;
    const int warp = tid >> 5, lane = tid & 31;
    const int g = lane >> 2, t = lane & 3;
    const int mg = warp & 3, ng = warp >> 2;
    const int R0 = mg * 32, C0 = ng * 64;
    const int row0 = blockIdx.x * 128;

    stage_w_async(smc, SM1_WH, SM1_WL, g_w1t_h, g_w1t_l, 128);

    if (tid < 128) {
        int r = row0 + tid;
        ((float*)(smc + SM1_CH))[tid] = (r < NH) ? rsqrtf(fmaxf((float)g_degi_he[r], 1.f)) : 0.f;
        ((float*)(smc + SM1_B1))[tid] = b1f[tid];
    }
#pragma unroll
    for (int i = tid; i < 4096; i += 256) {
        int r = i >> 5, c4 = (i & 31) * 4;
        float4 v = make_float4(0.f, 0.f, 0.f, 0.f);
        if (row0 + r < NH) v = *(const float4*)&g_hyper_acc[(row0 + r) * DD + c4];
        char* pH = smc + SM1_AH + r * STR + c4 * 2;
        char* pL = smc + SM1_AL + r * STR + c4 * 2;
        sts_hilo(pH, pL, v.x, v.y);
        sts_hilo(pH + 4, pL + 4, v.z, v.w);
    }
    W_WAIT();
    __syncthreads();

    float dA[2][8][4];
#pragma unroll
    for (int i = 0; i < 2; i++)
#pragma unroll
        for (int j = 0; j < 8; j++)
#pragma unroll
            for (int p = 0; p < 4; p++) dA[i][j][p] = 0.f;
    gemm32x64(smc, SM1_AH, SM1_AL, SM1_WH, SM1_WL, R0, C0, lane, dA);

    const float* b1s = (const float*)(smc + SM1_B1);
    const float* chs = (const float*)(smc + SM1_CH);
#pragma unroll
    for (int i = 0; i < 2; i++)
#pragma unroll
        for (int hh = 0; hh < 2; hh++) {
            int row = R0 + i * 16 + hh * 8 + g;
            int gr = row0 + row;
            if (gr >= NH) continue;
            float ch = chs[row];
            float chq = ch * ch;
#pragma unroll
            for (int j = 0; j < 8; j++) {
                int c = C0 + j * 8 + t * 2;
                float2 o;
                o.x = dA[i][j][hh * 2] * chq + b1s[c] * ch;
                o.y = dA[i][j][hh * 2 + 1] * chq + b1s[c + 1] * ch;
                *(float2*)&g_hyper_msg[gr * DD + c] = o;
            }
        }
}

// ---- fused GEMM2 + LN1 + FFN + LN2 (ping-pong W/hidden buffers) ----
#define SM_CN   0
#define SM_B2   512
#define SM_B4   1024
#define SM_G1   1536
#define SM_BE1  2048
#define SM_G2   2560
#define SM_BE2  3072
#define SM_B3   3584
#define SM_SUM  5632
#define SM_SQ   6656
#define SM_A1H  7680
#define SM_A1L  (SM_A1H + 128 * STR)
#define SM_P0H  (SM_A1L + 128 * STR)
#define SM_P0L  (SM_P0H + 128 * STR)
#define SM_P1H  (SM_P0L + 128 * STR)
#define SM_P1L  (SM_P1H + 128 * STR)
#define SM_TOTAL (SM_P1L + 128 * STR)

__global__ __launch_bounds__(256, 1) void k_fused_mma(
    const float* __restrict__ h, const float* __restrict__ b2f,
    const float* __restrict__ b3f, const float* __restrict__ b4f,
    const float* __restrict__ g1f, const float* __restrict__ be1f,
    const float* __restrict__ g2f, const float* __restrict__ be2f,
    float* __restrict__ out) {
    extern __shared__ char smc[];
    const int tid = threadIdx.x;
    const int warp = tid >> 5, lane = tid & 31;
    const int g = lane >> 2, t = lane & 3;
    const int mg = warp & 3, ng = warp >> 2;
    const int R0 = mg * 32, C0 = ng * 64;
    const int row0 = blockIdx.x * 128;

    stage_w_async(smc, SM_P0H, SM_P0L, g_w2t_h, g_w2t_l, 128);   // W2 -> P0

    if (tid < 128) {
        int r = row0 + tid;
        ((float*)(smc + SM_CN))[tid]  = (r < NN) ? rsqrtf(fmaxf((float)g_degi_node[r], 1.f)) : 0.f;
        ((float*)(smc + SM_B2))[tid]  = b2f[tid];
        ((float*)(smc + SM_B4))[tid]  = b4f[tid];
        ((float*)(smc + SM_G1))[tid]  = g1f[tid];
        ((float*)(smc + SM_BE1))[tid] = be1f[tid];
        ((float*)(smc + SM_G2))[tid]  = g2f[tid];
        ((float*)(smc + SM_BE2))[tid] = be2f[tid];
    }
    for (int i = tid; i < 512; i += 256) ((float*)(smc + SM_B3))[i] = b3f[i];

#pragma unroll
    for (int i = tid; i < 4096; i += 256) {
        int r = i >> 5, c4 = (i & 31) * 4;
        float4 v = make_float4(0.f, 0.f, 0.f, 0.f);
        if (row0 + r < NN) v = *(const float4*)&g_node_acc[(row0 + r) * DD + c4];
        char* pH = smc + SM_A1H + r * STR + c4 * 2;
        char* pL = smc + SM_A1L + r * STR + c4 * 2;
        sts_hilo(pH, pL, v.x, v.y);
        sts_hilo(pH + 4, pL + 4, v.z, v.w);
    }
    W_WAIT();
    __syncthreads();

    const float* cns = (const float*)(smc + SM_CN);
    float* sums = (float*)(smc + SM_SUM);   // [2][128]
    float* sqs  = (float*)(smc + SM_SQ);

    // ---- GEMM2 (reads P0=W2) ----
    float dA[2][8][4];
#pragma unroll
    for (int i = 0; i < 2; i++)
#pragma unroll
        for (int j = 0; j < 8; j++)
#pragma unroll
            for (int p = 0; p < 4; p++) dA[i][j][p] = 0.f;
    gemm32x64(smc, SM_A1H, SM_A1L, SM_P0H, SM_P0L, R0, C0, lane, dA);
    __syncthreads();                       // all warps done reading W2 (P0 free)
    stage_w_async(smc, SM_P0H, SM_P0L, g_w3t_h, g_w3t_l, 128);   // W3 chunk 0 -> P0, overlaps LN1

    // ---- epilogue: h1 = LN1(h + cn*D + b2) -> A1 planes ----
    {
        const float* b2s = (const float*)(smc + SM_B2);
        float rs[2][2], rq[2][2];
#pragma unroll
        for (int i = 0; i < 2; i++)
#pragma unroll
            for (int hh = 0; hh < 2; hh++) {
                int row = R0 + i * 16 + hh * 8 + g;
                int grow = row0 + row;
                float cn = cns[row];
                float s = 0.f, q = 0.f;
#pragma unroll
                for (int j = 0; j < 8; j++) {
                    int c = C0 + j * 8 + t * 2;
                    float2 hv = make_float2(0.f, 0.f);
                    if (grow < NN) hv = *(const float2*)&h[grow * DD + c];
                    float x0 = hv.x + cn * dA[i][j][hh * 2] + b2s[c];
                    float x1 = hv.y + cn * dA[i][j][hh * 2 + 1] + b2s[c + 1];
                    dA[i][j][hh * 2] = x0;
                    dA[i][j][hh * 2 + 1] = x1;
                    s += x0 + x1;
                    q += x0 * x0 + x1 * x1;
                }
                rs[i][hh] = s; rq[i][hh] = q;
            }
#pragma unroll
        for (int i = 0; i < 2; i++)
#pragma unroll
            for (int hh = 0; hh < 2; hh++) {
                rs[i][hh] += __shfl_xor_sync(~0u, rs[i][hh], 1);
                rs[i][hh] += __shfl_xor_sync(~0u, rs[i][hh], 2);
                rq[i][hh] += __shfl_xor_sync(~0u, rq[i][hh], 1);
                rq[i][hh] += __shfl_xor_sync(~0u, rq[i][hh], 2);
            }
        if (t == 0) {
#pragma unroll
            for (int i = 0; i < 2; i++)
#pragma unroll
                for (int hh = 0; hh < 2; hh++) {
                    int row = R0 + i * 16 + hh * 8 + g;
                    sums[ng * 128 + row] = rs[i][hh];
                    sqs[ng * 128 + row] = rq[i][hh];
                }
        }
        __syncthreads();
        const float* g1s = (const float*)(smc + SM_G1);
        const float* be1s = (const float*)(smc + SM_BE1);
#pragma unroll
        for (int i = 0; i < 2; i++)
#pragma unroll
            for (int hh = 0; hh < 2; hh++) {
                int row = R0 + i * 16 + hh * 8 + g;
                float ts = sums[row] + sums[128 + row];
                float tq = sqs[row] + sqs[128 + row];
                float mu = ts * (1.f / 128.f);
                float inv = rsqrtf(fmaxf(tq * (1.f / 128.f) - mu * mu, 0.f) + 1e-5f);
#pragma unroll
                for (int j = 0; j < 8; j++) {
                    int c = C0 + j * 8 + t * 2;
                    float y0 = (dA[i][j][hh * 2] - mu) * inv * g1s[c] + be1s[c];
                    float y1 = (dA[i][j][hh * 2 + 1] - mu) * inv * g1s[c + 1] + be1s[c + 1];
                    sts_hilo(smc + SM_A1H + row * STR + c * 2,
                             smc + SM_A1L + row * STR + c * 2, y0, y1);
                }
            }
    }
    W_WAIT();
    __syncthreads();    // W3 chunk 0 ready in P0 + A1(h1) visible

    // ---- FFN with ping-pong buffers ----
    float dC[2][8][4];
#pragma unroll
    for (int i = 0; i < 2; i++)
#pragma unroll
        for (int j = 0; j < 8; j++)
#pragma unroll
            for (int p = 0; p < 4; p++) dC[i][j][p] = 0.f;

    for (int nc = 0; nc < 4; nc++) {
        const int w3H = (nc & 1) ? SM_P1H : SM_P0H;
        const int w3L = (nc & 1) ? SM_P1L : SM_P0L;
        const int otH = (nc & 1) ? SM_P0H : SM_P1H;
        const int otL = (nc & 1) ? SM_P0L : SM_P1L;

        // stage W4(nc) into the other buffer; overlaps gemmA
        stage_w_async(smc, otH, otL, g_w4t_h + nc * 128, g_w4t_l + nc * 128, 512);

        float dB[2][8][4];
#pragma unroll
        for (int i = 0; i < 2; i++)
#pragma unroll
            for (int j = 0; j < 8; j++)
#pragma unroll
                for (int p = 0; p < 4; p++) dB[i][j][p] = 0.f;
        gemm32x64(smc, SM_A1H, SM_A1L, w3H, w3L, R0, C0, lane, dB);
        __syncthreads();                   // W3 chunk consumed (bufW3 free)

        // relu -> hidden into bufW3
        const float* b3s = (const float*)(smc + SM_B3) + nc * 128;
#pragma unroll
        for (int i = 0; i < 2; i++)
#pragma unroll
            for (int hh = 0; hh < 2; hh++) {
                int row = R0 + i * 16 + hh * 8 + g;
#pragma unroll
                for (int j = 0; j < 8; j++) {
                    int c = C0 + j * 8 + t * 2;
                    float x0 = fmaxf(dB[i][j][hh * 2] + b3s[c], 0.f);
                    float x1 = fmaxf(dB[i][j][hh * 2 + 1] + b3s[c + 1], 0.f);
                    sts_hilo(smc + w3H + row * STR + c * 2,
                             smc + w3L + row * STR + c * 2, x0, x1);
                }
            }
        W_WAIT();
        __syncthreads();                   // hidden visible + W4 ready
        gemm32x64(smc, w3H, w3L, otH, otL, R0, C0, lane, dC);
        if (nc < 3) {
            __syncthreads();               // W4 buffer free
            stage_w_async(smc, otH, otL,
                          g_w3t_h + (nc + 1) * 128 * DD, g_w3t_l + (nc + 1) * 128 * DD, 128);
            W_WAIT();
            __syncthreads();
        }
    }

    // ---- final epilogue: LN2(D2 + b4 + h1) -> out ----
    {
        const float* b4s = (const float*)(smc + SM_B4);
        float rs[2][2], rq[2][2];
#pragma unroll
        for (int i = 0; i < 2; i++)
#pragma unroll
            for (int hh = 0; hh < 2; hh++) {
                int row = R0 + i * 16 + hh * 8 + g;
                float s = 0.f, q = 0.f;
#pragma unroll
                for (int j = 0; j < 8; j++) {
                    int c = C0 + j * 8 + t * 2;
                    const char* pH = smc + SM_A1H + row * STR + c * 2;
                    const char* pL = smc + SM_A1L + row * STR + c * 2;
                    __nv_bfloat162 hh2 = *(const __nv_bfloat162*)(pH);
                    __nv_bfloat162 ll2 = *(const __nv_bfloat162*)(pL);
                    float x0 = dC[i][j][hh * 2] + b4s[c]
                             + __bfloat162float(hh2.x) + __bfloat162float(ll2.x);
                    float x1 = dC[i][j][hh * 2 + 1] + b4s[c + 1]
                             + __bfloat162float(hh2.y) + __bfloat162float(ll2.y);
                    dC[i][j][hh * 2] = x0;
                    dC[i][j][hh * 2 + 1] = x1;
                    s += x0 + x1;
                    q += x0 * x0 + x1 * x1;
                }
                rs[i][hh] = s; rq[i][hh] = q;
            }
#pragma unroll
        for (int i = 0; i < 2; i++)
#pragma unroll
            for (int hh = 0; hh < 2; hh++) {
                rs[i][hh] += __shfl_xor_sync(~0u, rs[i][hh], 1);
                rs[i][hh] += __shfl_xor_sync(~0u, rs[i][hh], 2);
                rq[i][hh] += __shfl_xor_sync(~0u, rq[i][hh], 1);
                rq[i][hh] += __shfl_xor_sync(~0u, rq[i][hh], 2);
            }
        if (t == 0) {
#pragma unroll
            for (int i = 0; i < 2; i++)
#pragma unroll
                for (int hh = 0; hh < 2; hh++) {
                    int row = R0 + i * 16 + hh * 8 + g;
                    sums[ng * 128 + row] = rs[i][hh];
                    sqs[ng * 128 + row] = rq[i][hh];
                }
        }
        __syncthreads();
        const float* g2s = (const float*)(smc + SM_G2);
        const float* be2s = (const float*)(smc + SM_BE2);
#pragma unroll
        for (int i = 0; i < 2; i++)
#pragma unroll
            for (int hh = 0; hh < 2; hh++) {
                int row = R0 + i * 16 + hh * 8 + g;
                int grow = row0 + row;
                float ts = sums[row] + sums[128 + row];
                float tq = sqs[row] + sqs[128 + row];
                float mu = ts * (1.f / 128.f);
                float inv = rsqrtf(fmaxf(tq * (1.f / 128.f) - mu * mu, 0.f) + 1e-5f);
                if (grow < NN) {
#pragma unroll
                    for (int j = 0; j < 8; j++) {
                        int c = C0 + j * 8 + t * 2;
                        float2 o;
                        o.x = (dC[i][j][hh * 2] - mu) * inv * g2s[c] + be2s[c];
                        o.y = (dC[i][j][hh * 2 + 1] - mu) * inv * g2s[c + 1] + be2s[c + 1];
                        *(float2*)&out[grow * DD + c] = o;
                    }
                }
            }
    }
}

// ---------------- launch ----------------
extern "C" void kernel_launch(void* const* d_in, const int* in_sizes, int n_in,
                              void* d_out, int out_size) {
    const float* h   = (const float*)d_in[0];
    const int*   src = (const int*)d_in[1];
    const int*   dst = (const int*)d_in[2];
    const float* W1  = (const float*)d_in[3];
    const float* b1  = (const float*)d_in[4];
    const float* W2  = (const float*)d_in[5];
    const float* b2  = (const float*)d_in[6];
    const float* W3  = (const float*)d_in[7];
    const float* b3  = (const float*)d_in[8];
    const float* W4  = (const float*)d_in[9];
    const float* b4  = (const float*)d_in[10];
    const float* g1  = (const float*)d_in[11];
    const float* be1 = (const float*)d_in[12];
    const float* g2  = (const float*)d_in[13];
    const float* be2 = (const float*)d_in[14];
    float* out = (float*)d_out;

    cudaFuncSetAttribute(k_gemm1_mma, cudaFuncAttributeMaxDynamicSharedMemorySize, SM1_TOTAL);
    cudaFuncSetAttribute(k_fused_mma, cudaFuncAttributeMaxDynamicSharedMemorySize, SM_TOTAL);

    k_init<<<288, 256>>>(W1, W2, W3, W4);
    k_deg<<<(NE / 4 + 255) / 256, 256>>>(src, dst);
    k_scan_p1<<<NB_HE + NB_NODE, 1024>>>();
    k_scan_p2p3<<<NB_HE + NB_NODE, 1024>>>();
    k_place<<<(NE / 4 + 255) / 256, 256>>>(src, dst);
    k_gather1<<<(NH * 32 + 255) / 256, 256>>>(h);
    k_gemm1_mma<<<(NH + 127) / 128, 256, SM1_TOTAL>>>(b1);
    k_gather2<<<(NN * 32 + 255) / 256, 256>>>();
    k_fused_mma<<<(NN + 127) / 128, 256, SM_TOTAL>>>(h, b2, b3, b4,
                                                     g1, be1, g2, be2, out);
}

// round 15
// speedup vs baseline: 1.0133x; 1.0133x over previous
#include <cuda_runtime.h>
#include <cuda_bf16.h>
#include <cstdint>

#define NN 100000
#define NH 20000
#define NE 1600000
#define DD 128
#define HH 512

#define NB_HE 20      // ceil(NH/1024)
#define NB_NODE 98    // ceil(NN/1024)

// ---------------- scratch (device globals; no allocation allowed) ----------------
__device__ __align__(16) int g_degi_node[NN];
__device__ __align__(16) int g_degi_he[NH];
__device__ __align__(16) int g_off_node[NN];   // after k_place: off[w] = orig off[w+1]
__device__ __align__(16) int g_off_he[NH];
__device__ __align__(16) int g_bsum[NB_HE + NB_NODE];
__device__ __align__(16) int g_srt_src[NE];     // edges sorted by dst -> src ids
__device__ __align__(16) int g_srt_dst[NE];     // edges sorted by src -> dst ids
__device__ __align__(16) float g_hyper_acc[NH * DD];
__device__ __align__(16) float g_hyper_msg[NH * DD];
__device__ __align__(16) float g_node_acc[NN * DD];
// pre-transposed bf16 hi/lo weight planes: [n][k] layout
__device__ __align__(16) __nv_bfloat16 g_w1t_h[DD * DD];
__device__ __align__(16) __nv_bfloat16 g_w1t_l[DD * DD];
__device__ __align__(16) __nv_bfloat16 g_w2t_h[DD * DD];
__device__ __align__(16) __nv_bfloat16 g_w2t_l[DD * DD];
__device__ __align__(16) __nv_bfloat16 g_w3t_h[HH * DD];   // [n=0..511][k=0..127]
__device__ __align__(16) __nv_bfloat16 g_w3t_l[HH * DD];
__device__ __align__(16) __nv_bfloat16 g_w4t_h[DD * HH];   // [n=0..127][kk=0..511]
__device__ __align__(16) __nv_bfloat16 g_w4t_l[DD * HH];

// =================== preprocessing kernels ===================
// blocks [0,160): tiled weight transpose+hi/lo; blocks [160,288): zero degree counters
__global__ void k_init(const float* __restrict__ W1, const float* __restrict__ W2,
                       const float* __restrict__ W3, const float* __restrict__ W4) {
    int b = blockIdx.x;
    if (b >= 160) {
        int idx = (b - 160) * 256 + threadIdx.x;
        int nthr = 128 * 256;
        for (int i = idx; i < NN; i += nthr) g_degi_node[i] = 0;
        for (int i = idx; i < NH; i += nthr) g_degi_he[i] = 0;
        return;
    }
    __shared__ float tile[32][33];
    const float* srcm;
    __nv_bfloat16 *dH, *dL;
    int kdim, ndim, local;
    if (b < 16)       { srcm = W1; dH = g_w1t_h; dL = g_w1t_l; kdim = 128; ndim = 128; local = b; }
    else if (b < 32)  { srcm = W2; dH = g_w2t_h; dL = g_w2t_l; kdim = 128; ndim = 128; local = b - 16; }
    else if (b < 96)  { srcm = W3; dH = g_w3t_h; dL = g_w3t_l; kdim = 128; ndim = 512; local = b - 32; }
    else              { srcm = W4; dH = g_w4t_h; dL = g_w4t_l; kdim = 512; ndim = 128; local = b - 96; }
    int ktiles = kdim >> 5;
    int kt = local % ktiles, nt = local / ktiles;
    int tx = threadIdx.x & 31, ty = threadIdx.x >> 5;
#pragma unroll
    for (int p = 0; p < 4; p++) {
        int r = p * 8 + ty;
        tile[r][tx] = srcm[(kt * 32 + r) * ndim + nt * 32 + tx];
    }
    __syncthreads();
#pragma unroll
    for (int p = 0; p < 4; p++) {
        int rr = p * 8 + ty;             // n-direction
        float v = tile[tx][rr];          // k = kt*32+tx
        __nv_bfloat16 hi = __float2bfloat16(v);
        int o = (nt * 32 + rr) * kdim + kt * 32 + tx;
        dH[o] = hi;
        dL[o] = __float2bfloat16(v - __bfloat162float(hi));
    }
}

__global__ void k_deg(const int* __restrict__ src, const int* __restrict__ dst) {
    int e = blockIdx.x * blockDim.x + threadIdx.x;
    if (e < NE) {
        atomicAdd(&g_degi_node[src[e]], 1);
        atomicAdd(&g_degi_he[dst[e]], 1);
    }
}

// ---- 2-pass multi-block exclusive scan (blocks 0..NB_HE-1: he, rest: node) ----
__global__ void k_scan_p1() {
    int b = blockIdx.x;
    const int* __restrict__ cnt;
    int* __restrict__ off;
    int n, lb;
    if (b < NB_HE) { cnt = g_degi_he; off = g_off_he; n = NH; lb = b; }
    else           { cnt = g_degi_node; off = g_off_node; n = NN; lb = b - NB_HE; }
    __shared__ int sh[1024];
    int tid = threadIdx.x;
    int i = lb * 1024 + tid;
    int v = (i < n) ? cnt[i] : 0;
    sh[tid] = v;
    __syncthreads();
    for (int o = 1; o < 1024; o <<= 1) {
        int t = (tid >= o) ? sh[tid - o] : 0;
        __syncthreads();
        sh[tid] += t;
        __syncthreads();
    }
    if (i < n) off[i] = sh[tid] - v;
    if (tid == 1023) g_bsum[b] = sh[1023];
}

// each block computes its base via parallel 128-thread reduction of block totals
__global__ void k_scan_p2p3() {
    __shared__ int red[128];
    int b = blockIdx.x;
    int* __restrict__ off;
    int n, lb, lo;
    if (b < NB_HE) { off = g_off_he; n = NH; lb = b; lo = 0; }
    else           { off = g_off_node; n = NN; lb = b - NB_HE; lo = NB_HE; }
    int tid = threadIdx.x;
    if (tid < 128) {
        int i = lo + tid;
        red[tid] = (i < b) ? g_bsum[i] : 0;
    }
    __syncthreads();
    if (tid < 64) red[tid] += red[tid + 64];
    __syncthreads();
    if (tid < 32) {
        int s = red[tid] + red[tid + 32];
#pragma unroll
        for (int o = 16; o; o >>= 1) s += __shfl_xor_sync(0xffffffffu, s, o);
        if (tid == 0) red[0] = s;
    }
    __syncthreads();
    int add = red[0];
    int i = lb * 1024 + tid;
    if (i < n) off[i] += add;
}

// atomicAdd directly on off: returned value is the slot; off[w] ends at orig off[w+1]
__global__ void k_place(const int* __restrict__ src, const int* __restrict__ dst) {
    int e = blockIdx.x * blockDim.x + threadIdx.x;
    if (e < NE) {
        int s = src[e], d = dst[e];
        int p1 = atomicAdd(&g_off_he[d], 1);
        g_srt_src[p1] = s;
        int p2 = atomicAdd(&g_off_node[s], 1);
        g_srt_dst[p2] = d;
    }
}

// =================== segmented gathers (no atomics) — R12 best-known form ========
__global__ void k_gather1(const float* __restrict__ h) {
    int w = (blockIdx.x * blockDim.x + threadIdx.x) >> 5;
    if (w >= NH) return;
    int lane = threadIdx.x & 31;
    int beg = w ? g_off_he[w - 1] : 0, end = g_off_he[w];
    float4 acc = make_float4(0.f, 0.f, 0.f, 0.f);
    int e = beg;
    while (end - e >= 32) {
        int idx = g_srt_src[e + lane];
        float cnl = rsqrtf(fmaxf((float)g_degi_node[idx], 1.f));
#pragma unroll
        for (int j = 0; j < 32; j++) {
            int s = __shfl_sync(0xffffffffu, idx, j);
            float c = __shfl_sync(0xffffffffu, cnl, j);
            float4 v = __ldg(&((const float4*)h)[s * 32 + lane]);
            acc.x = fmaf(c, v.x, acc.x);
            acc.y = fmaf(c, v.y, acc.y);
            acc.z = fmaf(c, v.z, acc.z);
            acc.w = fmaf(c, v.w, acc.w);
        }
        e += 32;
    }
    int n = end - e;
    if (n > 0) {
        int idx = g_srt_src[e + (lane < n ? lane : 0)];
        float cnl = rsqrtf(fmaxf((float)g_degi_node[idx], 1.f));
#pragma unroll 4
        for (int j = 0; j < n; j++) {
            int s = __shfl_sync(0xffffffffu, idx, j);
            float c = __shfl_sync(0xffffffffu, cnl, j);
            float4 v = __ldg(&((const float4*)h)[s * 32 + lane]);
            acc.x = fmaf(c, v.x, acc.x);
            acc.y = fmaf(c, v.y, acc.y);
            acc.z = fmaf(c, v.z, acc.z);
            acc.w = fmaf(c, v.w, acc.w);
        }
    }
    ((float4*)g_hyper_acc)[w * 32 + lane] = acc;
}

__global__ void k_gather2() {
    int w = (blockIdx.x * blockDim.x + threadIdx.x) >> 5;
    if (w >= NN) return;
    int lane = threadIdx.x & 31;
    int beg = w ? g_off_node[w - 1] : 0, end = g_off_node[w];
    float4 acc = make_float4(0.f, 0.f, 0.f, 0.f);
    int e = beg;
    while (end - e >= 32) {
        int idx = g_srt_dst[e + lane];
#pragma unroll
        for (int j = 0; j < 32; j++) {
            int d = __shfl_sync(0xffffffffu, idx, j);
            float4 v = __ldg(&((const float4*)g_hyper_msg)[d * 32 + lane]);
            acc.x += v.x; acc.y += v.y; acc.z += v.z; acc.w += v.w;
        }
        e += 32;
    }
    int n = end - e;
    if (n > 0) {
        int idx = g_srt_dst[e + (lane < n ? lane : 0)];
#pragma unroll 4
        for (int j = 0; j < n; j++) {
            int d = __shfl_sync(0xffffffffu, idx, j);
            float4 v = __ldg(&((const float4*)g_hyper_msg)[d * 32 + lane]);
            acc.x += v.x; acc.y += v.y; acc.z += v.z; acc.w += v.w;
        }
    }
    ((float4*)g_node_acc)[w * 32 + lane] = acc;
}

// =================== HMMA machinery ===================
#define STR 272

__device__ __forceinline__ void mma_bf16(float d[4], uint32_t a0, uint32_t a1,
                                         uint32_t a2, uint32_t a3,
                                         uint32_t b0, uint32_t b1) {
    asm volatile(
        "mma.sync.aligned.m16n8k16.row.col.f32.bf16.bf16.f32 "
        "{%0,%1,%2,%3}, {%4,%5,%6,%7}, {%8,%9}, {%0,%1,%2,%3};"
        : "+f"(d[0]), "+f"(d[1]), "+f"(d[2]), "+f"(d[3])
        : "r"(a0), "r"(a1), "r"(a2), "r"(a3), "r"(b0), "r"(b1));
}

__device__ __forceinline__ void ldsm_x4(uint32_t r[4], uint32_t a) {
    asm volatile("ldmatrix.sync.aligned.m8n8.x4.shared.b16 {%0,%1,%2,%3}, [%4];"
                 : "=r"(r[0]), "=r"(r[1]), "=r"(r[2]), "=r"(r[3]) : "r"(a));
}

__device__ __forceinline__ void sts_hilo(char* pH, char* pL, float x0, float x1) {
    __nv_bfloat16 h0 = __float2bfloat16(x0), h1 = __float2bfloat16(x1);
    float r0f = x0 - __bfloat162float(h0), r1f = x1 - __bfloat162float(h1);
    *(__nv_bfloat162*)pH = __halves2bfloat162(h0, h1);
    *(__nv_bfloat162*)pL = __halves2bfloat162(__float2bfloat16(r0f), __float2bfloat16(r1f));
}

// D[32 warp-rows x 64 warp-cols] += A[32x128] @ W^T[64x128], 3-term hi/lo, ldmatrix loads.
__device__ __forceinline__ void gemm32x64(const char* smc, int aHoff, int aLoff,
                                          int wHoff, int wLoff,
                                          int R0, int C0, int lane,
                                          float d[2][8][4]) {
    uint32_t base = (uint32_t)__cvta_generic_to_shared(smc);
    uint32_t aH = base + aHoff + (R0 + (lane & 15)) * STR + ((lane >> 4) & 1) * 16;
    uint32_t aL = aH + (aLoff - aHoff);
    int brow = C0 + (lane & 7) + ((lane >> 4) & 1) * 8;
    uint32_t bH = base + wHoff + brow * STR + ((lane >> 3) & 1) * 16;
    uint32_t bL = bH + (wLoff - wHoff);
#pragma unroll 2
    for (int k = 0; k < 8; k++) {
        uint32_t ah0[4], ah1[4], al0[4], al1[4];
        ldsm_x4(ah0, aH);
        ldsm_x4(ah1, aH + 16 * STR);
        ldsm_x4(al0, aL);
        ldsm_x4(al1, aL + 16 * STR);
#pragma unroll
        for (int jp = 0; jp < 4; jp++) {
            uint32_t bh[4], bl[4];
            ldsm_x4(bh, bH + jp * 16 * STR);
            ldsm_x4(bl, bL + jp * 16 * STR);
            int j0 = 2 * jp, j1 = 2 * jp + 1;
            mma_bf16(d[0][j0], ah0[0], ah0[1], ah0[2], ah0[3], bh[0], bh[1]);
            mma_bf16(d[0][j0], al0[0], al0[1], al0[2], al0[3], bh[0], bh[1]);
            mma_bf16(d[0][j0], ah0[0], ah0[1], ah0[2], ah0[3], bl[0], bl[1]);
            mma_bf16(d[1][j0], ah1[0], ah1[1], ah1[2], ah1[3], bh[0], bh[1]);
            mma_bf16(d[1][j0], al1[0], al1[1], al1[2], al1[3], bh[0], bh[1]);
            mma_bf16(d[1][j0], ah1[0], ah1[1], ah1[2], ah1[3], bl[0], bl[1]);
            mma_bf16(d[0][j1], ah0[0], ah0[1], ah0[2], ah0[3], bh[2], bh[3]);
            mma_bf16(d[0][j1], al0[0], al0[1], al0[2], al0[3], bh[2], bh[3]);
            mma_bf16(d[0][j1], ah0[0], ah0[1], ah0[2], ah0[3], bl[2], bl[3]);
            mma_bf16(d[1][j1], ah1[0], ah1[1], ah1[2], ah1[3], bh[2], bh[3]);
            mma_bf16(d[1][j1], al1[0], al1[1], al1[2], al1[3], bh[2], bh[3]);
            mma_bf16(d[1][j1], ah1[0], ah1[1], ah1[2], ah1[3], bl[2], bl[3]);
        }
        aH += 32; aL += 32; bH += 32; bL += 32;
    }
}

// async W staging: issue LDGSTS then overlap other work; wait with W_WAIT before use
__device__ __forceinline__ void stage_w_async(char* smc, int wHoff, int wLoff,
                                              const __nv_bfloat16* srcH,
                                              const __nv_bfloat16* srcL, int srcStride) {
    int tid = threadIdx.x;
    unsigned dH = (unsigned)__cvta_generic_to_shared(smc + wHoff);
    unsigned dL = (unsigned)__cvta_generic_to_shared(smc + wLoff);
#pragma unroll
    for (int i = tid; i < 2048; i += 256) {
        int r = i >> 4, c8 = (i & 15) * 8;
        asm volatile("cp.async.cg.shared.global [%0], [%1], 16;"
                     :: "r"(dH + r * STR + c8 * 2), "l"(srcH + r * srcStride + c8) : "memory");
        asm volatile("cp.async.cg.shared.global [%0], [%1], 16;"
                     :: "r"(dL + r * STR + c8 * 2), "l"(srcL + r * srcStride + c8) : "memory");
    }
    asm volatile("cp.async.commit_group;" ::: "memory");
}
#define W_WAIT() asm volatile("cp.async.wait_group 0;" ::: "memory")

// ---- GEMM1 (hyper): g_hyper_msg = ch^2*(hyper_acc @ W1) + ch*b1 ----
#define SM1_CH 0
#define SM1_B1 512
#define SM1_AH 1024
#define SM1_AL (SM1_AH + 128 * STR)
#define SM1_WH (SM1_AL + 128 * STR)
#define SM1_WL (SM1_WH + 128 * STR)
#define SM1_TOTAL (SM1_WL + 128 * STR)

__global__ __launch_bounds__(256, 1) void k_gemm1_mma(const float* __restrict__ b1f) {
    extern __shared__ char smc[];
    const int tid = threadIdx.x;
    const int warp = tid >> 5, lane = tid & 31;
    const int g = lane >> 2, t = lane & 3;
    const int mg = warp & 3, ng = warp >> 2;
    const int R0 = mg * 32, C0 = ng * 64;
    const int row0 = blockIdx.x * 128;

    stage_w_async(smc, SM1_WH, SM1_WL, g_w1t_h, g_w1t_l, 128);

    if (tid < 128) {
        int r = row0 + tid;
        ((float*)(smc + SM1_CH))[tid] = (r < NH) ? rsqrtf(fmaxf((float)g_degi_he[r], 1.f)) : 0.f;
        ((float*)(smc + SM1_B1))[tid] = b1f[tid];
    }
#pragma unroll
    for (int i = tid; i < 4096; i += 256) {
        int r = i >> 5, c4 = (i & 31) * 4;
        float4 v = make_float4(0.f, 0.f, 0.f, 0.f);
        if (row0 + r < NH) v = *(const float4*)&g_hyper_acc[(row0 + r) * DD + c4];
        char* pH = smc + SM1_AH + r * STR + c4 * 2;
        char* pL = smc + SM1_AL + r * STR + c4 * 2;
        sts_hilo(pH, pL, v.x, v.y);
        sts_hilo(pH + 4, pL + 4, v.z, v.w);
    }
    W_WAIT();
    __syncthreads();

    float dA[2][8][4];
#pragma unroll
    for (int i = 0; i < 2; i++)
#pragma unroll
        for (int j = 0; j < 8; j++)
#pragma unroll
            for (int p = 0; p < 4; p++) dA[i][j][p] = 0.f;
    gemm32x64(smc, SM1_AH, SM1_AL, SM1_WH, SM1_WL, R0, C0, lane, dA);

    const float* b1s = (const float*)(smc + SM1_B1);
    const float* chs = (const float*)(smc + SM1_CH);
#pragma unroll
    for (int i = 0; i < 2; i++)
#pragma unroll
        for (int hh = 0; hh < 2; hh++) {
            int row = R0 + i * 16 + hh * 8 + g;
            int gr = row0 + row;
            if (gr >= NH) continue;
            float ch = chs[row];
            float chq = ch * ch;
#pragma unroll
            for (int j = 0; j < 8; j++) {
                int c = C0 + j * 8 + t * 2;
                float2 o;
                o.x = dA[i][j][hh * 2] * chq + b1s[c] * ch;
                o.y = dA[i][j][hh * 2 + 1] * chq + b1s[c + 1] * ch;
                *(float2*)&g_hyper_msg[gr * DD + c] = o;
            }
        }
}

// ---- fused GEMM2 + LN1 + FFN + LN2 (ping-pong W/hidden buffers) ----
#define SM_CN   0
#define SM_B2   512
#define SM_B4   1024
#define SM_G1   1536
#define SM_BE1  2048
#define SM_G2   2560
#define SM_BE2  3072
#define SM_B3   3584
#define SM_SUM  5632
#define SM_SQ   6656
#define SM_A1H  7680
#define SM_A1L  (SM_A1H + 128 * STR)
#define SM_P0H  (SM_A1L + 128 * STR)
#define SM_P0L  (SM_P0H + 128 * STR)
#define SM_P1H  (SM_P0L + 128 * STR)
#define SM_P1L  (SM_P1H + 128 * STR)
#define SM_TOTAL (SM_P1L + 128 * STR)

__global__ __launch_bounds__(256, 1) void k_fused_mma(
    const float* __restrict__ h, const float* __restrict__ b2f,
    const float* __restrict__ b3f, const float* __restrict__ b4f,
    const float* __restrict__ g1f, const float* __restrict__ be1f,
    const float* __restrict__ g2f, const float* __restrict__ be2f,
    float* __restrict__ out) {
    extern __shared__ char smc[];
    const int tid = threadIdx.x;
    const int warp = tid >> 5, lane = tid & 31;
    const int g = lane >> 2, t = lane & 3;
    const int mg = warp & 3, ng = warp >> 2;
    const int R0 = mg * 32, C0 = ng * 64;
    const int row0 = blockIdx.x * 128;

    stage_w_async(smc, SM_P0H, SM_P0L, g_w2t_h, g_w2t_l, 128);   // W2 -> P0

    if (tid < 128) {
        int r = row0 + tid;
        ((float*)(smc + SM_CN))[tid]  = (r < NN) ? rsqrtf(fmaxf((float)g_degi_node[r], 1.f)) : 0.f;
        ((float*)(smc + SM_B2))[tid]  = b2f[tid];
        ((float*)(smc + SM_B4))[tid]  = b4f[tid];
        ((float*)(smc + SM_G1))[tid]  = g1f[tid];
        ((float*)(smc + SM_BE1))[tid] = be1f[tid];
        ((float*)(smc + SM_G2))[tid]  = g2f[tid];
        ((float*)(smc + SM_BE2))[tid] = be2f[tid];
    }
    for (int i = tid; i < 512; i += 256) ((float*)(smc + SM_B3))[i] = b3f[i];

#pragma unroll
    for (int i = tid; i < 4096; i += 256) {
        int r = i >> 5, c4 = (i & 31) * 4;
        float4 v = make_float4(0.f, 0.f, 0.f, 0.f);
        if (row0 + r < NN) v = *(const float4*)&g_node_acc[(row0 + r) * DD + c4];
        char* pH = smc + SM_A1H + r * STR + c4 * 2;
        char* pL = smc + SM_A1L + r * STR + c4 * 2;
        sts_hilo(pH, pL, v.x, v.y);
        sts_hilo(pH + 4, pL + 4, v.z, v.w);
    }
    W_WAIT();
    __syncthreads();

    const float* cns = (const float*)(smc + SM_CN);
    float* sums = (float*)(smc + SM_SUM);   // [2][128]
    float* sqs  = (float*)(smc + SM_SQ);

    // ---- GEMM2 (reads P0=W2) ----
    float dA[2][8][4];
#pragma unroll
    for (int i = 0; i < 2; i++)
#pragma unroll
        for (int j = 0; j < 8; j++)
#pragma unroll
            for (int p = 0; p < 4; p++) dA[i][j][p] = 0.f;
    gemm32x64(smc, SM_A1H, SM_A1L, SM_P0H, SM_P0L, R0, C0, lane, dA);
    __syncthreads();                       // all warps done reading W2 (P0 free)
    stage_w_async(smc, SM_P0H, SM_P0L, g_w3t_h, g_w3t_l, 128);   // W3 chunk 0 -> P0, overlaps LN1

    // ---- epilogue: h1 = LN1(h + cn*D + b2) -> A1 planes ----
    {
        const float* b2s = (const float*)(smc + SM_B2);
        float rs[2][2], rq[2][2];
#pragma unroll
        for (int i = 0; i < 2; i++)
#pragma unroll
            for (int hh = 0; hh < 2; hh++) {
                int row = R0 + i * 16 + hh * 8 + g;
                int grow = row0 + row;
                float cn = cns[row];
                float s = 0.f, q = 0.f;
#pragma unroll
                for (int j = 0; j < 8; j++) {
                    int c = C0 + j * 8 + t * 2;
                    float2 hv = make_float2(0.f, 0.f);
                    if (grow < NN) hv = *(const float2*)&h[grow * DD + c];
                    float x0 = hv.x + cn * dA[i][j][hh * 2] + b2s[c];
                    float x1 = hv.y + cn * dA[i][j][hh * 2 + 1] + b2s[c + 1];
                    dA[i][j][hh * 2] = x0;
                    dA[i][j][hh * 2 + 1] = x1;
                    s += x0 + x1;
                    q += x0 * x0 + x1 * x1;
                }
                rs[i][hh] = s; rq[i][hh] = q;
            }
#pragma unroll
        for (int i = 0; i < 2; i++)
#pragma unroll
            for (int hh = 0; hh < 2; hh++) {
                rs[i][hh] += __shfl_xor_sync(~0u, rs[i][hh], 1);
                rs[i][hh] += __shfl_xor_sync(~0u, rs[i][hh], 2);
                rq[i][hh] += __shfl_xor_sync(~0u, rq[i][hh], 1);
                rq[i][hh] += __shfl_xor_sync(~0u, rq[i][hh], 2);
            }
        if (t == 0) {
#pragma unroll
            for (int i = 0; i < 2; i++)
#pragma unroll
                for (int hh = 0; hh < 2; hh++) {
                    int row = R0 + i * 16 + hh * 8 + g;
                    sums[ng * 128 + row] = rs[i][hh];
                    sqs[ng * 128 + row] = rq[i][hh];
                }
        }
        __syncthreads();
        const float* g1s = (const float*)(smc + SM_G1);
        const float* be1s = (const float*)(smc + SM_BE1);
#pragma unroll
        for (int i = 0; i < 2; i++)
#pragma unroll
            for (int hh = 0; hh < 2; hh++) {
                int row = R0 + i * 16 + hh * 8 + g;
                float ts = sums[row] + sums[128 + row];
                float tq = sqs[row] + sqs[128 + row];
                float mu = ts * (1.f / 128.f);
                float inv = rsqrtf(fmaxf(tq * (1.f / 128.f) - mu * mu, 0.f) + 1e-5f);
#pragma unroll
                for (int j = 0; j < 8; j++) {
                    int c = C0 + j * 8 + t * 2;
                    float y0 = (dA[i][j][hh * 2] - mu) * inv * g1s[c] + be1s[c];
                    float y1 = (dA[i][j][hh * 2 + 1] - mu) * inv * g1s[c + 1] + be1s[c + 1];
                    sts_hilo(smc + SM_A1H + row * STR + c * 2,
                             smc + SM_A1L + row * STR + c * 2, y0, y1);
                }
            }
    }
    W_WAIT();
    __syncthreads();    // W3 chunk 0 ready in P0 + A1(h1) visible

    // ---- FFN with ping-pong buffers ----
    float dC[2][8][4];
#pragma unroll
    for (int i = 0; i < 2; i++)
#pragma unroll
        for (int j = 0; j < 8; j++)
#pragma unroll
            for (int p = 0; p < 4; p++) dC[i][j][p] = 0.f;

    for (int nc = 0; nc < 4; nc++) {
        const int w3H = (nc & 1) ? SM_P1H : SM_P0H;
        const int w3L = (nc & 1) ? SM_P1L : SM_P0L;
        const int otH = (nc & 1) ? SM_P0H : SM_P1H;
        const int otL = (nc & 1) ? SM_P0L : SM_P1L;

        // stage W4(nc) into the other buffer; overlaps gemmA
        stage_w_async(smc, otH, otL, g_w4t_h + nc * 128, g_w4t_l + nc * 128, 512);

        float dB[2][8][4];
#pragma unroll
        for (int i = 0; i < 2; i++)
#pragma unroll
            for (int j = 0; j < 8; j++)
#pragma unroll
                for (int p = 0; p < 4; p++) dB[i][j][p] = 0.f;
        gemm32x64(smc, SM_A1H, SM_A1L, w3H, w3L, R0, C0, lane, dB);
        __syncthreads();                   // W3 chunk consumed (bufW3 free)

        // relu -> hidden into bufW3
        const float* b3s = (const float*)(smc + SM_B3) + nc * 128;
#pragma unroll
        for (int i = 0; i < 2; i++)
#pragma unroll
            for (int hh = 0; hh < 2; hh++) {
                int row = R0 + i * 16 + hh * 8 + g;
#pragma unroll
                for (int j = 0; j < 8; j++) {
                    int c = C0 + j * 8 + t * 2;
                    float x0 = fmaxf(dB[i][j][hh * 2] + b3s[c], 0.f);
                    float x1 = fmaxf(dB[i][j][hh * 2 + 1] + b3s[c + 1], 0.f);
                    sts_hilo(smc + w3H + row * STR + c * 2,
                             smc + w3L + row * STR + c * 2, x0, x1);
                }
            }
        W_WAIT();
        __syncthreads();                   // hidden visible + W4 ready
        gemm32x64(smc, w3H, w3L, otH, otL, R0, C0, lane, dC);
        if (nc < 3) {
            __syncthreads();               // W4 buffer free
            stage_w_async(smc, otH, otL,
                          g_w3t_h + (nc + 1) * 128 * DD, g_w3t_l + (nc + 1) * 128 * DD, 128);
            W_WAIT();
            __syncthreads();
        }
    }

    // ---- final epilogue: LN2(D2 + b4 + h1) -> out ----
    {
        const float* b4s = (const float*)(smc + SM_B4);
        float rs[2][2], rq[2][2];
#pragma unroll
        for (int i = 0; i < 2; i++)
#pragma unroll
            for (int hh = 0; hh < 2; hh++) {
                int row = R0 + i * 16 + hh * 8 + g;
                float s = 0.f, q = 0.f;
#pragma unroll
                for (int j = 0; j < 8; j++) {
                    int c = C0 + j * 8 + t * 2;
                    const char* pH = smc + SM_A1H + row * STR + c * 2;
                    const char* pL = smc + SM_A1L + row * STR + c * 2;
                    __nv_bfloat162 hh2 = *(const __nv_bfloat162*)(pH);
                    __nv_bfloat162 ll2 = *(const __nv_bfloat162*)(pL);
                    float x0 = dC[i][j][hh * 2] + b4s[c]
                             + __bfloat162float(hh2.x) + __bfloat162float(ll2.x);
                    float x1 = dC[i][j][hh * 2 + 1] + b4s[c + 1]
                             + __bfloat162float(hh2.y) + __bfloat162float(ll2.y);
                    dC[i][j][hh * 2] = x0;
                    dC[i][j][hh * 2 + 1] = x1;
                    s += x0 + x1;
                    q += x0 * x0 + x1 * x1;
                }
                rs[i][hh] = s; rq[i][hh] = q;
            }
#pragma unroll
        for (int i = 0; i < 2; i++)
#pragma unroll
            for (int hh = 0; hh < 2; hh++) {
                rs[i][hh] += __shfl_xor_sync(~0u, rs[i][hh], 1);
                rs[i][hh] += __shfl_xor_sync(~0u, rs[i][hh], 2);
                rq[i][hh] += __shfl_xor_sync(~0u, rq[i][hh], 1);
                rq[i][hh] += __shfl_xor_sync(~0u, rq[i][hh], 2);
            }
        if (t == 0) {
#pragma unroll
            for (int i = 0; i < 2; i++)
#pragma unroll
                for (int hh = 0; hh < 2; hh++) {
                    int row = R0 + i * 16 + hh * 8 + g;
                    sums[ng * 128 + row] = rs[i][hh];
                    sqs[ng * 128 + row] = rq[i][hh];
                }
        }
        __syncthreads();
        const float* g2s = (const float*)(smc + SM_G2);
        const float* be2s = (const float*)(smc + SM_BE2);
#pragma unroll
        for (int i = 0; i < 2; i++)
#pragma unroll
            for (int hh = 0; hh < 2; hh++) {
                int row = R0 + i * 16 + hh * 8 + g;
                int grow = row0 + row;
                float ts = sums[row] + sums[128 + row];
                float tq = sqs[row] + sqs[128 + row];
                float mu = ts * (1.f / 128.f);
                float inv = rsqrtf(fmaxf(tq * (1.f / 128.f) - mu * mu, 0.f) + 1e-5f);
                if (grow < NN) {
#pragma unroll
                    for (int j = 0; j < 8; j++) {
                        int c = C0 + j * 8 + t * 2;
                        float2 o;
                        o.x = (dC[i][j][hh * 2] - mu) * inv * g2s[c] + be2s[c];
                        o.y = (dC[i][j][hh * 2 + 1] - mu) * inv * g2s[c + 1] + be2s[c + 1];
                        *(float2*)&out[grow * DD + c] = o;
                    }
                }
            }
    }
}

// ---------------- launch ----------------
extern "C" void kernel_launch(void* const* d_in, const int* in_sizes, int n_in,
                              void* d_out, int out_size) {
    const float* h   = (const float*)d_in[0];
    const int*   src = (const int*)d_in[1];
    const int*   dst = (const int*)d_in[2];
    const float* W1  = (const float*)d_in[3];
    const float* b1  = (const float*)d_in[4];
    const float* W2  = (const float*)d_in[5];
    const float* b2  = (const float*)d_in[6];
    const float* W3  = (const float*)d_in[7];
    const float* b3  = (const float*)d_in[8];
    const float* W4  = (const float*)d_in[9];
    const float* b4  = (const float*)d_in[10];
    const float* g1  = (const float*)d_in[11];
    const float* be1 = (const float*)d_in[12];
    const float* g2  = (const float*)d_in[13];
    const float* be2 = (const float*)d_in[14];
    float* out = (float*)d_out;

    cudaFuncSetAttribute(k_gemm1_mma, cudaFuncAttributeMaxDynamicSharedMemorySize, SM1_TOTAL);
    cudaFuncSetAttribute(k_fused_mma, cudaFuncAttributeMaxDynamicSharedMemorySize, SM_TOTAL);

    k_init<<<288, 256>>>(W1, W2, W3, W4);
    k_deg<<<(NE + 255) / 256, 256>>>(src, dst);
    k_scan_p1<<<NB_HE + NB_NODE, 1024>>>();
    k_scan_p2p3<<<NB_HE + NB_NODE, 1024>>>();
    k_place<<<(NE + 255) / 256, 256>>>(src, dst);
    k_gather1<<<(NH * 32 + 255) / 256, 256>>>(h);
    k_gemm1_mma<<<(NH + 127) / 128, 256, SM1_TOTAL>>>(b1);
    k_gather2<<<(NN * 32 + 255) / 256, 256>>>();
    k_fused_mma<<<(NN + 127) / 128, 256, SM_TOTAL>>>(h, b2, b3, b4,
                                                     g1, be1, g2, be2, out);
}

// round 16
// speedup vs baseline: 1.0642x; 1.0502x over previous
#include <cuda_runtime.h>
#include <cuda_bf16.h>
#include <cstdint>

#define NN 100000
#define NH 20000
#define NE 1600000
#define DD 128
#define HH 512

#define NB_HE 20      // ceil(NH/1024)
#define NB_NODE 98    // ceil(NN/1024)

// ---------------- scratch (device globals; no allocation allowed) ----------------
__device__ __align__(16) int g_degi_node[NN];
__device__ __align__(16) int g_degi_he[NH];
__device__ __align__(16) int g_off_node[NN];   // after k_place: off[w] = orig off[w+1]
__device__ __align__(16) int g_off_he[NH];
__device__ __align__(16) int g_bsum[NB_HE + NB_NODE];
__device__ __align__(16) int g_srt_src[NE];     // edges sorted by dst -> src ids
__device__ __align__(16) int g_srt_dst[NE];     // edges sorted by src -> dst ids
__device__ __align__(16) __nv_bfloat16 g_hs_bf[NN * DD];       // bf16(cn * h)
__device__ __align__(16) __nv_bfloat16 g_hyper_msg_bf[NH * DD]; // bf16 messages
__device__ __align__(16) float g_hyper_acc[NH * DD];
__device__ __align__(16) float g_node_acc[NN * DD];
// pre-transposed bf16 hi/lo weight planes: [n][k] layout
__device__ __align__(16) __nv_bfloat16 g_w1t_h[DD * DD];
__device__ __align__(16) __nv_bfloat16 g_w1t_l[DD * DD];
__device__ __align__(16) __nv_bfloat16 g_w2t_h[DD * DD];
__device__ __align__(16) __nv_bfloat16 g_w2t_l[DD * DD];
__device__ __align__(16) __nv_bfloat16 g_w3t_h[HH * DD];   // [n=0..511][k=0..127]
__device__ __align__(16) __nv_bfloat16 g_w3t_l[HH * DD];
__device__ __align__(16) __nv_bfloat16 g_w4t_h[DD * HH];   // [n=0..127][kk=0..511]
__device__ __align__(16) __nv_bfloat16 g_w4t_l[DD * HH];

// =================== preprocessing kernels ===================
// blocks [0,160): tiled weight transpose+hi/lo; blocks [160,288): zero degree counters
__global__ void k_init(const float* __restrict__ W1, const float* __restrict__ W2,
                       const float* __restrict__ W3, const float* __restrict__ W4) {
    int b = blockIdx.x;
    if (b >= 160) {
        int idx = (b - 160) * 256 + threadIdx.x;
        int nthr = 128 * 256;
        for (int i = idx; i < NN; i += nthr) g_degi_node[i] = 0;
        for (int i = idx; i < NH; i += nthr) g_degi_he[i] = 0;
        return;
    }
    __shared__ float tile[32][33];
    const float* srcm;
    __nv_bfloat16 *dH, *dL;
    int kdim, ndim, local;
    if (b < 16)       { srcm = W1; dH = g_w1t_h; dL = g_w1t_l; kdim = 128; ndim = 128; local = b; }
    else if (b < 32)  { srcm = W2; dH = g_w2t_h; dL = g_w2t_l; kdim = 128; ndim = 128; local = b - 16; }
    else if (b < 96)  { srcm = W3; dH = g_w3t_h; dL = g_w3t_l; kdim = 128; ndim = 512; local = b - 32; }
    else              { srcm = W4; dH = g_w4t_h; dL = g_w4t_l; kdim = 512; ndim = 128; local = b - 96; }
    int ktiles = kdim >> 5;
    int kt = local % ktiles, nt = local / ktiles;
    int tx = threadIdx.x & 31, ty = threadIdx.x >> 5;
#pragma unroll
    for (int p = 0; p < 4; p++) {
        int r = p * 8 + ty;
        tile[r][tx] = srcm[(kt * 32 + r) * ndim + nt * 32 + tx];
    }
    __syncthreads();
#pragma unroll
    for (int p = 0; p < 4; p++) {
        int rr = p * 8 + ty;             // n-direction
        float v = tile[tx][rr];          // k = kt*32+tx
        __nv_bfloat16 hi = __float2bfloat16(v);
        int o = (nt * 32 + rr) * kdim + kt * 32 + tx;
        dH[o] = hi;
        dL[o] = __float2bfloat16(v - __bfloat162float(hi));
    }
}

__global__ void k_deg(const int* __restrict__ src, const int* __restrict__ dst) {
    int e = blockIdx.x * blockDim.x + threadIdx.x;
    if (e < NE) {
        atomicAdd(&g_degi_node[src[e]], 1);
        atomicAdd(&g_degi_he[dst[e]], 1);
    }
}

// g_hs_bf = bf16(cn * h)  (runs after k_deg)
__global__ void k_hs(const float* __restrict__ h) {
    int i = blockIdx.x * blockDim.x + threadIdx.x;
    if (i < NN * 32) {
        int r = i >> 5;
        float cn = rsqrtf(fmaxf((float)g_degi_node[r], 1.f));
        float4 v = __ldg(&((const float4*)h)[i]);
        uint2 o;
        __nv_bfloat162 p0 = __floats2bfloat162_rn(v.x * cn, v.y * cn);
        __nv_bfloat162 p1 = __floats2bfloat162_rn(v.z * cn, v.w * cn);
        o.x = *(uint32_t*)&p0;
        o.y = *(uint32_t*)&p1;
        ((uint2*)g_hs_bf)[i] = o;
    }
}

// ---- 2-pass multi-block exclusive scan (blocks 0..NB_HE-1: he, rest: node) ----
__global__ void k_scan_p1() {
    int b = blockIdx.x;
    const int* __restrict__ cnt;
    int* __restrict__ off;
    int n, lb;
    if (b < NB_HE) { cnt = g_degi_he; off = g_off_he; n = NH; lb = b; }
    else           { cnt = g_degi_node; off = g_off_node; n = NN; lb = b - NB_HE; }
    __shared__ int sh[1024];
    int tid = threadIdx.x;
    int i = lb * 1024 + tid;
    int v = (i < n) ? cnt[i] : 0;
    sh[tid] = v;
    __syncthreads();
    for (int o = 1; o < 1024; o <<= 1) {
        int t = (tid >= o) ? sh[tid - o] : 0;
        __syncthreads();
        sh[tid] += t;
        __syncthreads();
    }
    if (i < n) off[i] = sh[tid] - v;
    if (tid == 1023) g_bsum[b] = sh[1023];
}

// each block computes its base via parallel 128-thread reduction of block totals
__global__ void k_scan_p2p3() {
    __shared__ int red[128];
    int b = blockIdx.x;
    int* __restrict__ off;
    int n, lb, lo;
    if (b < NB_HE) { off = g_off_he; n = NH; lb = b; lo = 0; }
    else           { off = g_off_node; n = NN; lb = b - NB_HE; lo = NB_HE; }
    int tid = threadIdx.x;
    if (tid < 128) {
        int i = lo + tid;
        red[tid] = (i < b) ? g_bsum[i] : 0;
    }
    __syncthreads();
    if (tid < 64) red[tid] += red[tid + 64];
    __syncthreads();
    if (tid < 32) {
        int s = red[tid] + red[tid + 32];
#pragma unroll
        for (int o = 16; o; o >>= 1) s += __shfl_xor_sync(0xffffffffu, s, o);
        if (tid == 0) red[0] = s;
    }
    __syncthreads();
    int add = red[0];
    int i = lb * 1024 + tid;
    if (i < n) off[i] += add;
}

// atomicAdd directly on off: returned value is the slot; off[w] ends at orig off[w+1]
__global__ void k_place(const int* __restrict__ src, const int* __restrict__ dst) {
    int e = blockIdx.x * blockDim.x + threadIdx.x;
    if (e < NE) {
        int s = src[e], d = dst[e];
        int p1 = atomicAdd(&g_off_he[d], 1);
        g_srt_src[p1] = s;
        int p2 = atomicAdd(&g_off_node[s], 1);
        g_srt_dst[p2] = d;
    }
}

// =================== segmented gathers (bf16 tables, fp32 accumulate) ========
__device__ __forceinline__ void acc_bf4(float4& acc, uint2 u) {
    __nv_bfloat162 p0 = *(__nv_bfloat162*)&u.x;
    __nv_bfloat162 p1 = *(__nv_bfloat162*)&u.y;
    float2 f0 = __bfloat1622float2(p0);
    float2 f1 = __bfloat1622float2(p1);
    acc.x += f0.x; acc.y += f0.y; acc.z += f1.x; acc.w += f1.y;
}

__global__ void k_gather1() {
    int w = (blockIdx.x * blockDim.x + threadIdx.x) >> 5;
    if (w >= NH) return;
    int lane = threadIdx.x & 31;
    int beg = w ? g_off_he[w - 1] : 0, end = g_off_he[w];
    const uint2* hsb = (const uint2*)g_hs_bf;
    float4 acc = make_float4(0.f, 0.f, 0.f, 0.f);
    int e = beg;
    while (end - e >= 32) {
        int idx = g_srt_src[e + lane];
#pragma unroll
        for (int j = 0; j < 32; j++) {
            int s = __shfl_sync(0xffffffffu, idx, j);
            acc_bf4(acc, __ldg(&hsb[s * 32 + lane]));
        }
        e += 32;
    }
    int n = end - e;
    if (n > 0) {
        int idx = g_srt_src[e + (lane < n ? lane : 0)];
#pragma unroll 4
        for (int j = 0; j < n; j++) {
            int s = __shfl_sync(0xffffffffu, idx, j);
            acc_bf4(acc, __ldg(&hsb[s * 32 + lane]));
        }
    }
    ((float4*)g_hyper_acc)[w * 32 + lane] = acc;
}

__global__ void k_gather2() {
    int w = (blockIdx.x * blockDim.x + threadIdx.x) >> 5;
    if (w >= NN) return;
    int lane = threadIdx.x & 31;
    int beg = w ? g_off_node[w - 1] : 0, end = g_off_node[w];
    const uint2* msb = (const uint2*)g_hyper_msg_bf;
    float4 acc = make_float4(0.f, 0.f, 0.f, 0.f);
    int e = beg;
    while (end - e >= 32) {
        int idx = g_srt_dst[e + lane];
#pragma unroll
        for (int j = 0; j < 32; j++) {
            int d = __shfl_sync(0xffffffffu, idx, j);
            acc_bf4(acc, __ldg(&msb[d * 32 + lane]));
        }
        e += 32;
    }
    int n = end - e;
    if (n > 0) {
        int idx = g_srt_dst[e + (lane < n ? lane : 0)];
#pragma unroll 4
        for (int j = 0; j < n; j++) {
            int d = __shfl_sync(0xffffffffu, idx, j);
            acc_bf4(acc, __ldg(&msb[d * 32 + lane]));
        }
    }
    ((float4*)g_node_acc)[w * 32 + lane] = acc;
}

// =================== HMMA machinery ===================
#define STR 272

__device__ __forceinline__ void mma_bf16(float d[4], uint32_t a0, uint32_t a1,
                                         uint32_t a2, uint32_t a3,
                                         uint32_t b0, uint32_t b1) {
    asm volatile(
        "mma.sync.aligned.m16n8k16.row.col.f32.bf16.bf16.f32 "
        "{%0,%1,%2,%3}, {%4,%5,%6,%7}, {%8,%9}, {%0,%1,%2,%3};"
        : "+f"(d[0]), "+f"(d[1]), "+f"(d[2]), "+f"(d[3])
        : "r"(a0), "r"(a1), "r"(a2), "r"(a3), "r"(b0), "r"(b1));
}

__device__ __forceinline__ void ldsm_x4(uint32_t r[4], uint32_t a) {
    asm volatile("ldmatrix.sync.aligned.m8n8.x4.shared.b16 {%0,%1,%2,%3}, [%4];"
                 : "=r"(r[0]), "=r"(r[1]), "=r"(r[2]), "=r"(r[3]) : "r"(a));
}

__device__ __forceinline__ void sts_hilo(char* pH, char* pL, float x0, float x1) {
    __nv_bfloat16 h0 = __float2bfloat16(x0), h1 = __float2bfloat16(x1);
    float r0f = x0 - __bfloat162float(h0), r1f = x1 - __bfloat162float(h1);
    *(__nv_bfloat162*)pH = __halves2bfloat162(h0, h1);
    *(__nv_bfloat162*)pL = __halves2bfloat162(__float2bfloat16(r0f), __float2bfloat16(r1f));
}

// D[32 warp-rows x 64 warp-cols] += A[32x128] @ W^T[64x128], 3-term hi/lo, ldmatrix loads.
__device__ __forceinline__ void gemm32x64(const char* smc, int aHoff, int aLoff,
                                          int wHoff, int wLoff,
                                          int R0, int C0, int lane,
                                          float d[2][8][4]) {
    uint32_t base = (uint32_t)__cvta_generic_to_shared(smc);
    uint32_t aH = base + aHoff + (R0 + (lane & 15)) * STR + ((lane >> 4) & 1) * 16;
    uint32_t aL = aH + (aLoff - aHoff);
    int brow = C0 + (lane & 7) + ((lane >> 4) & 1) * 8;
    uint32_t bH = base + wHoff + brow * STR + ((lane >> 3) & 1) * 16;
    uint32_t bL = bH + (wLoff - wHoff);
#pragma unroll 2
    for (int k = 0; k < 8; k++) {
        uint32_t ah0[4], ah1[4], al0[4], al1[4];
        ldsm_x4(ah0, aH);
        ldsm_x4(ah1, aH + 16 * STR);
        ldsm_x4(al0, aL);
        ldsm_x4(al1, aL + 16 * STR);
#pragma unroll
        for (int jp = 0; jp < 4; jp++) {
            uint32_t bh[4], bl[4];
            ldsm_x4(bh, bH + jp * 16 * STR);
            ldsm_x4(bl, bL + jp * 16 * STR);
            int j0 = 2 * jp, j1 = 2 * jp + 1;
            mma_bf16(d[0][j0], ah0[0], ah0[1], ah0[2], ah0[3], bh[0], bh[1]);
            mma_bf16(d[0][j0], al0[0], al0[1], al0[2], al0[3], bh[0], bh[1]);
            mma_bf16(d[0][j0], ah0[0], ah0[1], ah0[2], ah0[3], bl[0], bl[1]);
            mma_bf16(d[1][j0], ah1[0], ah1[1], ah1[2], ah1[3], bh[0], bh[1]);
            mma_bf16(d[1][j0], al1[0], al1[1], al1[2], al1[3], bh[0], bh[1]);
            mma_bf16(d[1][j0], ah1[0], ah1[1], ah1[2], ah1[3], bl[0], bl[1]);
            mma_bf16(d[0][j1], ah0[0], ah0[1], ah0[2], ah0[3], bh[2], bh[3]);
            mma_bf16(d[0][j1], al0[0], al0[1], al0[2], al0[3], bh[2], bh[3]);
            mma_bf16(d[0][j1], ah0[0], ah0[1], ah0[2], ah0[3], bl[2], bl[3]);
            mma_bf16(d[1][j1], ah1[0], ah1[1], ah1[2], ah1[3], bh[2], bh[3]);
            mma_bf16(d[1][j1], al1[0], al1[1], al1[2], al1[3], bh[2], bh[3]);
            mma_bf16(d[1][j1], ah1[0], ah1[1], ah1[2], ah1[3], bl[2], bl[3]);
        }
        aH += 32; aL += 32; bH += 32; bL += 32;
    }
}

// async W staging: issue LDGSTS then overlap other work; wait with W_WAIT before use
__device__ __forceinline__ void stage_w_async(char* smc, int wHoff, int wLoff,
                                              const __nv_bfloat16* srcH,
                                              const __nv_bfloat16* srcL, int srcStride) {
    int tid = threadIdx.x;
    unsigned dH = (unsigned)__cvta_generic_to_shared(smc + wHoff);
    unsigned dL = (unsigned)__cvta_generic_to_shared(smc + wLoff);
#pragma unroll
    for (int i = tid; i < 2048; i += 256) {
        int r = i >> 4, c8 = (i & 15) * 8;
        asm volatile("cp.async.cg.shared.global [%0], [%1], 16;"
                     :: "r"(dH + r * STR + c8 * 2), "l"(srcH + r * srcStride + c8) : "memory");
        asm volatile("cp.async.cg.shared.global [%0], [%1], 16;"
                     :: "r"(dL + r * STR + c8 * 2), "l"(srcL + r * srcStride + c8) : "memory");
    }
    asm volatile("cp.async.commit_group;" ::: "memory");
}
#define W_WAIT() asm volatile("cp.async.wait_group 0;" ::: "memory")

// ---- GEMM1 (hyper): g_hyper_msg_bf = bf16(ch^2*(hyper_acc @ W1) + ch*b1) ----
#define SM1_CH 0
#define SM1_B1 512
#define SM1_AH 1024
#define SM1_AL (SM1_AH + 128 * STR)
#define SM1_WH (SM1_AL + 128 * STR)
#define SM1_WL (SM1_WH + 128 * STR)
#define SM1_TOTAL (SM1_WL + 128 * STR)

__global__ __launch_bounds__(256, 1) void k_gemm1_mma(const float* __restrict__ b1f) {
    extern __shared__ char smc[];
    const int tid = threadIdx.x;
    const int warp = tid >> 5, lane = tid & 31;
    const int g = lane >> 2, t = lane & 3;
    const int mg = warp & 3, ng = warp >> 2;
    const int R0 = mg * 32, C0 = ng * 64;
    const int row0 = blockIdx.x * 128;

    stage_w_async(smc, SM1_WH, SM1_WL, g_w1t_h, g_w1t_l, 128);

    if (tid < 128) {
        int r = row0 + tid;
        ((float*)(smc + SM1_CH))[tid] = (r < NH) ? rsqrtf(fmaxf((float)g_degi_he[r], 1.f)) : 0.f;
        ((float*)(smc + SM1_B1))[tid] = b1f[tid];
    }
#pragma unroll
    for (int i = tid; i < 4096; i += 256) {
        int r = i >> 5, c4 = (i & 31) * 4;
        float4 v = make_float4(0.f, 0.f, 0.f, 0.f);
        if (row0 + r < NH) v = *(const float4*)&g_hyper_acc[(row0 + r) * DD + c4];
        char* pH = smc + SM1_AH + r * STR + c4 * 2;
        char* pL = smc + SM1_AL + r * STR + c4 * 2;
        sts_hilo(pH, pL, v.x, v.y);
        sts_hilo(pH + 4, pL + 4, v.z, v.w);
    }
    W_WAIT();
    __syncthreads();

    float dA[2][8][4];
#pragma unroll
    for (int i = 0; i < 2; i++)
#pragma unroll
        for (int j = 0; j < 8; j++)
#pragma unroll
            for (int p = 0; p < 4; p++) dA[i][j][p] = 0.f;
    gemm32x64(smc, SM1_AH, SM1_AL, SM1_WH, SM1_WL, R0, C0, lane, dA);

    const float* b1s = (const float*)(smc + SM1_B1);
    const float* chs = (const float*)(smc + SM1_CH);
#pragma unroll
    for (int i = 0; i < 2; i++)
#pragma unroll
        for (int hh = 0; hh < 2; hh++) {
            int row = R0 + i * 16 + hh * 8 + g;
            int gr = row0 + row;
            if (gr >= NH) continue;
            float ch = chs[row];
            float chq = ch * ch;
#pragma unroll
            for (int j = 0; j < 8; j++) {
                int c = C0 + j * 8 + t * 2;
                float ox = dA[i][j][hh * 2] * chq + b1s[c] * ch;
                float oy = dA[i][j][hh * 2 + 1] * chq + b1s[c + 1] * ch;
                *(__nv_bfloat162*)&g_hyper_msg_bf[gr * DD + c] = __floats2bfloat162_rn(ox, oy);
            }
        }
}

// ---- fused GEMM2 + LN1 + FFN + LN2 (ping-pong W/hidden buffers) ----
#define SM_CN   0
#define SM_B2   512
#define SM_B4   1024
#define SM_G1   1536
#define SM_BE1  2048
#define SM_G2   2560
#define SM_BE2  3072
#define SM_B3   3584
#define SM_SUM  5632
#define SM_SQ   6656
#define SM_A1H  7680
#define SM_A1L  (SM_A1H + 128 * STR)
#define SM_P0H  (SM_A1L + 128 * STR)
#define SM_P0L  (SM_P0H + 128 * STR)
#define SM_P1H  (SM_P0L + 128 * STR)
#define SM_P1L  (SM_P1H + 128 * STR)
#define SM_TOTAL (SM_P1L + 128 * STR)

__global__ __launch_bounds__(256, 1) void k_fused_mma(
    const float* __restrict__ h, const float* __restrict__ b2f,
    const float* __restrict__ b3f, const float* __restrict__ b4f,
    const float* __restrict__ g1f, const float* __restrict__ be1f,
    const float* __restrict__ g2f, const float* __restrict__ be2f,
    float* __restrict__ out) {
    extern __shared__ char smc[];
    const int tid = threadIdx.x;
    const int warp = tid >> 5, lane = tid & 31;
    const int g = lane >> 2, t = lane & 3;
    const int mg = warp & 3, ng = warp >> 2;
    const int R0 = mg * 32, C0 = ng * 64;
    const int row0 = blockIdx.x * 128;

    stage_w_async(smc, SM_P0H, SM_P0L, g_w2t_h, g_w2t_l, 128);   // W2 -> P0

    if (tid < 128) {
        int r = row0 + tid;
        ((float*)(smc + SM_CN))[tid]  = (r < NN) ? rsqrtf(fmaxf((float)g_degi_node[r], 1.f)) : 0.f;
        ((float*)(smc + SM_B2))[tid]  = b2f[tid];
        ((float*)(smc + SM_B4))[tid]  = b4f[tid];
        ((float*)(smc + SM_G1))[tid]  = g1f[tid];
        ((float*)(smc + SM_BE1))[tid] = be1f[tid];
        ((float*)(smc + SM_G2))[tid]  = g2f[tid];
        ((float*)(smc + SM_BE2))[tid] = be2f[tid];
    }
    for (int i = tid; i < 512; i += 256) ((float*)(smc + SM_B3))[i] = b3f[i];

#pragma unroll
    for (int i = tid; i < 4096; i += 256) {
        int r = i >> 5, c4 = (i & 31) * 4;
        float4 v = make_float4(0.f, 0.f, 0.f, 0.f);
        if (row0 + r < NN) v = *(const float4*)&g_node_acc[(row0 + r) * DD + c4];
        char* pH = smc + SM_A1H + r * STR + c4 * 2;
        char* pL = smc + SM_A1L + r * STR + c4 * 2;
        sts_hilo(pH, pL, v.x, v.y);
        sts_hilo(pH + 4, pL + 4, v.z, v.w);
    }
    W_WAIT();
    __syncthreads();

    const float* cns = (const float*)(smc + SM_CN);
    float* sums = (float*)(smc + SM_SUM);   // [2][128]
    float* sqs  = (float*)(smc + SM_SQ);

    // ---- GEMM2 (reads P0=W2) ----
    float dA[2][8][4];
#pragma unroll
    for (int i = 0; i < 2; i++)
#pragma unroll
        for (int j = 0; j < 8; j++)
#pragma unroll
            for (int p = 0; p < 4; p++) dA[i][j][p] = 0.f;
    gemm32x64(smc, SM_A1H, SM_A1L, SM_P0H, SM_P0L, R0, C0, lane, dA);
    __syncthreads();                       // all warps done reading W2 (P0 free)
    stage_w_async(smc, SM_P0H, SM_P0L, g_w3t_h, g_w3t_l, 128);   // W3 chunk 0 -> P0, overlaps LN1

    // ---- epilogue: h1 = LN1(h + cn*D + b2) -> A1 planes ----
    {
        const float* b2s = (const float*)(smc + SM_B2);
        float rs[2][2], rq[2][2];
#pragma unroll
        for (int i = 0; i < 2; i++)
#pragma unroll
            for (int hh = 0; hh < 2; hh++) {
                int row = R0 + i * 16 + hh * 8 + g;
                int grow = row0 + row;
                float cn = cns[row];
                float s = 0.f, q = 0.f;
#pragma unroll
                for (int j = 0; j < 8; j++) {
                    int c = C0 + j * 8 + t * 2;
                    float2 hv = make_float2(0.f, 0.f);
                    if (grow < NN) hv = *(const float2*)&h[grow * DD + c];
                    float x0 = hv.x + cn * dA[i][j][hh * 2] + b2s[c];
                    float x1 = hv.y + cn * dA[i][j][hh * 2 + 1] + b2s[c + 1];
                    dA[i][j][hh * 2] = x0;
                    dA[i][j][hh * 2 + 1] = x1;
                    s += x0 + x1;
                    q += x0 * x0 + x1 * x1;
                }
                rs[i][hh] = s; rq[i][hh] = q;
            }
#pragma unroll
        for (int i = 0; i < 2; i++)
#pragma unroll
            for (int hh = 0; hh < 2; hh++) {
                rs[i][hh] += __shfl_xor_sync(~0u, rs[i][hh], 1);
                rs[i][hh] += __shfl_xor_sync(~0u, rs[i][hh], 2);
                rq[i][hh] += __shfl_xor_sync(~0u, rq[i][hh], 1);
                rq[i][hh] += __shfl_xor_sync(~0u, rq[i][hh], 2);
            }
        if (t == 0) {
#pragma unroll
            for (int i = 0; i < 2; i++)
#pragma unroll
                for (int hh = 0; hh < 2; hh++) {
                    int row = R0 + i * 16 + hh * 8 + g;
                    sums[ng * 128 + row] = rs[i][hh];
                    sqs[ng * 128 + row] = rq[i][hh];
                }
        }
        __syncthreads();
        const float* g1s = (const float*)(smc + SM_G1);
        const float* be1s = (const float*)(smc + SM_BE1);
#pragma unroll
        for (int i = 0; i < 2; i++)
#pragma unroll
            for (int hh = 0; hh < 2; hh++) {
                int row = R0 + i * 16 + hh * 8 + g;
                float ts = sums[row] + sums[128 + row];
                float tq = sqs[row] + sqs[128 + row];
                float mu = ts * (1.f / 128.f);
                float inv = rsqrtf(fmaxf(tq * (1.f / 128.f) - mu * mu, 0.f) + 1e-5f);
#pragma unroll
                for (int j = 0; j < 8; j++) {
                    int c = C0 + j * 8 + t * 2;
                    float y0 = (dA[i][j][hh * 2] - mu) * inv * g1s[c] + be1s[c];
                    float y1 = (dA[i][j][hh * 2 + 1] - mu) * inv * g1s[c + 1] + be1s[c + 1];
                    sts_hilo(smc + SM_A1H + row * STR + c * 2,
                             smc + SM_A1L + row * STR + c * 2, y0, y1);
                }
            }
    }
    W_WAIT();
    __syncthreads();    // W3 chunk 0 ready in P0 + A1(h1) visible

    // ---- FFN with ping-pong buffers ----
    float dC[2][8][4];
#pragma unroll
    for (int i = 0; i < 2; i++)
#pragma unroll
        for (int j = 0; j < 8; j++)
#pragma unroll
            for (int p = 0; p < 4; p++) dC[i][j][p] = 0.f;

    for (int nc = 0; nc < 4; nc++) {
        const int w3H = (nc & 1) ? SM_P1H : SM_P0H;
        const int w3L = (nc & 1) ? SM_P1L : SM_P0L;
        const int otH = (nc & 1) ? SM_P0H : SM_P1H;
        const int otL = (nc & 1) ? SM_P0L : SM_P1L;

        // stage W4(nc) into the other buffer; overlaps gemmA
        stage_w_async(smc, otH, otL, g_w4t_h + nc * 128, g_w4t_l + nc * 128, 512);

        float dB[2][8][4];
#pragma unroll
        for (int i = 0; i < 2; i++)
#pragma unroll
            for (int j = 0; j < 8; j++)
#pragma unroll
                for (int p = 0; p < 4; p++) dB[i][j][p] = 0.f;
        gemm32x64(smc, SM_A1H, SM_A1L, w3H, w3L, R0, C0, lane, dB);
        __syncthreads();                   // W3 chunk consumed (bufW3 free)

        // relu -> hidden into bufW3
        const float* b3s = (const float*)(smc + SM_B3) + nc * 128;
#pragma unroll
        for (int i = 0; i < 2; i++)
#pragma unroll
            for (int hh = 0; hh < 2; hh++) {
                int row = R0 + i * 16 + hh * 8 + g;
#pragma unroll
                for (int j = 0; j < 8; j++) {
                    int c = C0 + j * 8 + t * 2;
                    float x0 = fmaxf(dB[i][j][hh * 2] + b3s[c], 0.f);
                    float x1 = fmaxf(dB[i][j][hh * 2 + 1] + b3s[c + 1], 0.f);
                    sts_hilo(smc + w3H + row * STR + c * 2,
                             smc + w3L + row * STR + c * 2, x0, x1);
                }
            }
        W_WAIT();
        __syncthreads();                   // hidden visible + W4 ready
        gemm32x64(smc, w3H, w3L, otH, otL, R0, C0, lane, dC);
        if (nc < 3) {
            __syncthreads();               // W4 buffer free
            stage_w_async(smc, otH, otL,
                          g_w3t_h + (nc + 1) * 128 * DD, g_w3t_l + (nc + 1) * 128 * DD, 128);
            W_WAIT();
            __syncthreads();
        }
    }

    // ---- final epilogue: LN2(D2 + b4 + h1) -> out ----
    {
        const float* b4s = (const float*)(smc + SM_B4);
        float rs[2][2], rq[2][2];
#pragma unroll
        for (int i = 0; i < 2; i++)
#pragma unroll
            for (int hh = 0; hh < 2; hh++) {
                int row = R0 + i * 16 + hh * 8 + g;
                float s = 0.f, q = 0.f;
#pragma unroll
                for (int j = 0; j < 8; j++) {
                    int c = C0 + j * 8 + t * 2;
                    const char* pH = smc + SM_A1H + row * STR + c * 2;
                    const char* pL = smc + SM_A1L + row * STR + c * 2;
                    __nv_bfloat162 hh2 = *(const __nv_bfloat162*)(pH);
                    __nv_bfloat162 ll2 = *(const __nv_bfloat162*)(pL);
                    float x0 = dC[i][j][hh * 2] + b4s[c]
                             + __bfloat162float(hh2.x) + __bfloat162float(ll2.x);
                    float x1 = dC[i][j][hh * 2 + 1] + b4s[c + 1]
                             + __bfloat162float(hh2.y) + __bfloat162float(ll2.y);
                    dC[i][j][hh * 2] = x0;
                    dC[i][j][hh * 2 + 1] = x1;
                    s += x0 + x1;
                    q += x0 * x0 + x1 * x1;
                }
                rs[i][hh] = s; rq[i][hh] = q;
            }
#pragma unroll
        for (int i = 0; i < 2; i++)
#pragma unroll
            for (int hh = 0; hh < 2; hh++) {
                rs[i][hh] += __shfl_xor_sync(~0u, rs[i][hh], 1);
                rs[i][hh] += __shfl_xor_sync(~0u, rs[i][hh], 2);
                rq[i][hh] += __shfl_xor_sync(~0u, rq[i][hh], 1);
                rq[i][hh] += __shfl_xor_sync(~0u, rq[i][hh], 2);
            }
        if (t == 0) {
#pragma unroll
            for (int i = 0; i < 2; i++)
#pragma unroll
                for (int hh = 0; hh < 2; hh++) {
                    int row = R0 + i * 16 + hh * 8 + g;
                    sums[ng * 128 + row] = rs[i][hh];
                    sqs[ng * 128 + row] = rq[i][hh];
                }
        }
        __syncthreads();
        const float* g2s = (const float*)(smc + SM_G2);
        const float* be2s = (const float*)(smc + SM_BE2);
#pragma unroll
        for (int i = 0; i < 2; i++)
#pragma unroll
            for (int hh = 0; hh < 2; hh++) {
                int row = R0 + i * 16 + hh * 8 + g;
                int grow = row0 + row;
                float ts = sums[row] + sums[128 + row];
                float tq = sqs[row] + sqs[128 + row];
                float mu = ts * (1.f / 128.f);
                float inv = rsqrtf(fmaxf(tq * (1.f / 128.f) - mu * mu, 0.f) + 1e-5f);
                if (grow < NN) {
#pragma unroll
                    for (int j = 0; j < 8; j++) {
                        int c = C0 + j * 8 + t * 2;
                        float2 o;
                        o.x = (dC[i][j][hh * 2] - mu) * inv * g2s[c] + be2s[c];
                        o.y = (dC[i][j][hh * 2 + 1] - mu) * inv * g2s[c + 1] + be2s[c + 1];
                        *(float2*)&out[grow * DD + c] = o;
                    }
                }
            }
    }
}

// ---------------- launch ----------------
extern "C" void kernel_launch(void* const* d_in, const int* in_sizes, int n_in,
                              void* d_out, int out_size) {
    const float* h   = (const float*)d_in[0];
    const int*   src = (const int*)d_in[1];
    const int*   dst = (const int*)d_in[2];
    const float* W1  = (const float*)d_in[3];
    const float* b1  = (const float*)d_in[4];
    const float* W2  = (const float*)d_in[5];
    const float* b2  = (const float*)d_in[6];
    const float* W3  = (const float*)d_in[7];
    const float* b3  = (const float*)d_in[8];
    const float* W4  = (const float*)d_in[9];
    const float* b4  = (const float*)d_in[10];
    const float* g1  = (const float*)d_in[11];
    const float* be1 = (const float*)d_in[12];
    const float* g2  = (const float*)d_in[13];
    const float* be2 = (const float*)d_in[14];
    float* out = (float*)d_out;

    cudaFuncSetAttribute(k_gemm1_mma, cudaFuncAttributeMaxDynamicSharedMemorySize, SM1_TOTAL);
    cudaFuncSetAttribute(k_fused_mma, cudaFuncAttributeMaxDynamicSharedMemorySize, SM_TOTAL);

    k_init<<<288, 256>>>(W1, W2, W3, W4);
    k_deg<<<(NE + 255) / 256, 256>>>(src, dst);
    k_hs<<<(NN * 32 + 255) / 256, 256>>>(h);
    k_scan_p1<<<NB_HE + NB_NODE, 1024>>>();
    k_scan_p2p3<<<NB_HE + NB_NODE, 1024>>>();
    k_place<<<(NE + 255) / 256, 256>>>(src, dst);
    k_gather1<<<(NH * 32 + 255) / 256, 256>>>();
    k_gemm1_mma<<<(NH + 127) / 128, 256, SM1_TOTAL>>>(b1);
    k_gather2<<<(NN * 32 + 255) / 256, 256>>>();
    k_fused_mma<<<(NN + 127) / 128, 256, SM_TOTAL>>>(h, b2, b3, b4,
                                                     g1, be1, g2, be2, out);
}